// round 1
// baseline (speedup 1.0000x reference)
#include <cuda_runtime.h>
#include <math.h>

#define Bq 4
#define Tt 12
#define Pp 196
#define Dd 512
#define Hh 8
#define DHd 64
#define EPSV 1e-6f

#define M1 (Bq*Tt*Pp)            // 9408
#define ROWS_AV (Bq*Tt*Tt*Pp)    // 112896
#define POSMOD (Tt*Tt*Pp)        // 28224

// ---------------- scratch (device globals; no allocations allowed) ----------
__device__ float g_x2[M1*Dd];
__device__ float g_q [M1*Dd];
__device__ float g_k [M1*Dd];
__device__ float g_v [M1*Dd];
__device__ float g_av[(size_t)ROWS_AV*Dd];
__device__ float g_xres[M1*Dd];
__device__ float g_h [M1*2*Dd];
__device__ float g_btsum[Dd];

// ---------------- helpers ----------------
__device__ __forceinline__ float gelu_exact(float x) {
    return 0.5f * x * (1.0f + erff(x * 0.70710678118654752f));
}

// ---------------- bt sum: btsum[e] = sum_u bt[u,e] ----------------
__global__ void btsum_k(const float* __restrict__ bt) {
    int e = blockIdx.x * blockDim.x + threadIdx.x;
    if (e < Dd) {
        float s = 0.f;
        #pragma unroll
        for (int u = 0; u < Tt; u++) s += bt[u * Dd + e];
        g_btsum[e] = s;
    }
}

// ---------------- LayerNorm (ddof=1, (sd+eps) denom), optional +pos --------
// one block (256 threads) per row of 512; each thread owns a float2
__global__ void ln_k(const float* __restrict__ in,
                     const float* __restrict__ al,
                     const float* __restrict__ be,
                     const float* __restrict__ pos,
                     float* __restrict__ out,
                     int posmod) {
    int row = blockIdx.x;
    int tid = threadIdx.x;
    const float2* rin = (const float2*)(in + (size_t)row * Dd);
    float2 v = rin[tid];
    float s  = v.x + v.y;
    float sq = v.x * v.x + v.y * v.y;
    #pragma unroll
    for (int o = 16; o; o >>= 1) {
        s  += __shfl_xor_sync(0xffffffffu, s,  o);
        sq += __shfl_xor_sync(0xffffffffu, sq, o);
    }
    __shared__ float ss[8], ssq[8];
    int w = tid >> 5;
    if ((tid & 31) == 0) { ss[w] = s; ssq[w] = sq; }
    __syncthreads();
    s = 0.f; sq = 0.f;
    #pragma unroll
    for (int i = 0; i < 8; i++) { s += ss[i]; sq += ssq[i]; }
    float mu  = s * (1.0f / Dd);
    float var = (sq - (float)Dd * mu * mu) * (1.0f / (Dd - 1));
    float inv = 1.0f / (sqrtf(fmaxf(var, 0.f)) + EPSV);

    float2 a = ((const float2*)al)[tid];
    float2 b = ((const float2*)be)[tid];
    float2 o;
    o.x = a.x * (v.x - mu) * inv + b.x;
    o.y = a.y * (v.y - mu) * inv + b.y;
    if (pos) {
        const float2* pr = (const float2*)(pos + (size_t)(row % posmod) * Dd);
        float2 p = pr[tid];
        o.x += p.x; o.y += p.y;
    }
    ((float2*)(out + (size_t)row * Dd))[tid] = o;
}

// ---------------- generic GEMM: C[m,n] = epi(scale*sum_k A[m,k]*B[n,k] + bias[n])
// A: [M,K] row-major, B: [N,K] row-major. 64x64 tile, BK=16, 256 threads, 4x4/thread
__global__ void gemm_k(const float* __restrict__ A,
                       const float* __restrict__ Bm,
                       const float* __restrict__ bias,
                       const float* __restrict__ res,  // optional residual [M,N]
                       float* __restrict__ C,
                       int M, int N, int K, float scale, int act) {
    __shared__ float As[16 * 65];
    __shared__ float Bs[16 * 65];
    int tid = threadIdx.x;
    int tx = tid & 15, ty = tid >> 4;
    int bm = blockIdx.y * 64, bn = blockIdx.x * 64;
    float acc[4][4] = {};
    const float* Ab = A  + (size_t)bm * K;
    const float* Bb = Bm + (size_t)bn * K;
    for (int k0 = 0; k0 < K; k0 += 16) {
        #pragma unroll
        for (int i = 0; i < 4; i++) {
            int idx = tid + i * 256;
            int m = idx >> 4, kk = idx & 15;
            As[kk * 65 + m] = Ab[(size_t)m * K + k0 + kk];
            Bs[kk * 65 + m] = Bb[(size_t)m * K + k0 + kk];
        }
        __syncthreads();
        #pragma unroll
        for (int kk = 0; kk < 16; kk++) {
            float a[4], b[4];
            #pragma unroll
            for (int i = 0; i < 4; i++) a[i] = As[kk * 65 + ty * 4 + i];
            #pragma unroll
            for (int j = 0; j < 4; j++) b[j] = Bs[kk * 65 + tx * 4 + j];
            #pragma unroll
            for (int i = 0; i < 4; i++)
                #pragma unroll
                for (int j = 0; j < 4; j++)
                    acc[i][j] += a[i] * b[j];
        }
        __syncthreads();
    }
    #pragma unroll
    for (int i = 0; i < 4; i++) {
        int m = bm + ty * 4 + i;
        #pragma unroll
        for (int j = 0; j < 4; j++) {
            int n = bn + tx * 4 + j;
            float v = acc[i][j] * scale + bias[n];
            if (act) v = gelu_exact(v);
            if (res) v += res[(size_t)m * N + n];
            C[(size_t)m * N + n] = v;
        }
    }
}

// ---------------- tc GEMM: M=9408, N=512, K=6144 (k = u*512+d) -------------
// A[m,(u,d)] = Y[((b*T+t)*T+u)*P*512 + p*512 + d]  (Y = LN(av)+pos)
// B[(u,d),e] = Wt[u*512*512 + e*512 + d]
// epilogue: xres = x + gelu(acc/T + btsum[e])
__global__ void gemm_tc_k(const float* __restrict__ Y,
                          const float* __restrict__ Wt,
                          const float* __restrict__ xin) {
    const int K = Tt * Dd;     // 6144
    __shared__ float As[16 * 65];
    __shared__ float Bs[16 * 65];
    __shared__ size_t rowbase[64];
    int tid = threadIdx.x;
    int tx = tid & 15, ty = tid >> 4;
    int bm = blockIdx.y * 64, bn = blockIdx.x * 64;
    if (tid < 64) {
        int m = bm + tid;
        int b = m / (Tt * Pp);
        int r = m % (Tt * Pp);
        int t = r / Pp;
        int p = r % Pp;
        rowbase[tid] = ((size_t)(b * (Tt * Tt) + t * Tt)) * (Pp * Dd) + (size_t)p * Dd;
    }
    __syncthreads();
    float acc[4][4] = {};
    for (int k0 = 0; k0 < K; k0 += 16) {
        int u = k0 >> 9;
        int dbase = k0 & 511;
        #pragma unroll
        for (int i = 0; i < 4; i++) {
            int idx = tid + i * 256;
            int m = idx >> 4, kk = idx & 15;
            As[kk * 65 + m] = Y[rowbase[m] + (size_t)u * (Pp * Dd) + dbase + kk];
            Bs[kk * 65 + m] = Wt[(size_t)u * (Dd * Dd) + (size_t)(bn + m) * Dd + dbase + kk];
        }
        __syncthreads();
        #pragma unroll
        for (int kk = 0; kk < 16; kk++) {
            float a[4], b[4];
            #pragma unroll
            for (int i = 0; i < 4; i++) a[i] = As[kk * 65 + ty * 4 + i];
            #pragma unroll
            for (int j = 0; j < 4; j++) b[j] = Bs[kk * 65 + tx * 4 + j];
            #pragma unroll
            for (int i = 0; i < 4; i++)
                #pragma unroll
                for (int j = 0; j < 4; j++)
                    acc[i][j] += a[i] * b[j];
        }
        __syncthreads();
    }
    #pragma unroll
    for (int i = 0; i < 4; i++) {
        int m = bm + ty * 4 + i;
        #pragma unroll
        for (int j = 0; j < 4; j++) {
            int n = bn + tx * 4 + j;
            float v = acc[i][j] * (1.0f / Tt) + g_btsum[n];
            g_xres[(size_t)m * Dd + n] = xin[(size_t)m * Dd + n] + gelu_exact(v);
        }
    }
}

// ---------------- fused attention: one block per (b,t,u,h) ----------------
// smem: K,V tiles [196][68] + per-warp q[68] and probs[200]
#define SMEM_ATTN_FLOATS (196*68*2 + 8*68 + 8*200)
__global__ void attn_k() {
    int bid = blockIdx.x;
    int h = bid & 7;
    int u = (bid >> 3) % Tt;
    int t = (bid / (Hh * Tt)) % Tt;
    int b = bid / (Hh * Tt * Tt);

    extern __shared__ float sm[];
    float* Ks = sm;
    float* Vs = Ks + 196 * 68;
    float* qs = Vs + 196 * 68;
    float* ps = qs + 8 * 68;

    int tid  = threadIdx.x;  // 256
    int w    = tid >> 5;
    int lane = tid & 31;

    const float* Kb = g_k + ((size_t)(b * Tt + u) * Pp) * Dd + h * DHd;
    const float* Vb = g_v + ((size_t)(b * Tt + u) * Pp) * Dd + h * DHd;
    const float* Qb = g_q + ((size_t)(b * Tt + t) * Pp) * Dd + h * DHd;
    float*       Ob = g_av + ((size_t)((b * Tt + t) * Tt + u) * Pp) * Dd + h * DHd;

    for (int idx = tid; idx < Pp * DHd; idx += 256) {
        int l = idx >> 6, d = idx & 63;
        Ks[l * 68 + d] = Kb[(size_t)l * Dd + d];
        Vs[l * 68 + d] = Vb[(size_t)l * Dd + d];
    }
    __syncthreads();

    for (int p = w; p < Pp; p += 8) {
        if (lane < 16)
            ((float4*)(qs + w * 68))[lane] = ((const float4*)(Qb + (size_t)p * Dd))[lane];
        __syncwarp();
        // scores
        for (int kb = lane; kb < Pp; kb += 32) {
            const float4* kp = (const float4*)(Ks + kb * 68);
            const float4* qp = (const float4*)(qs + w * 68);
            float acc = 0.f;
            #pragma unroll
            for (int i = 0; i < 16; i++) {
                float4 kk = kp[i];
                float4 qq = qp[i];
                acc += kk.x * qq.x + kk.y * qq.y + kk.z * qq.z + kk.w * qq.w;
            }
            ps[w * 200 + kb] = acc * 0.125f;  // 1/sqrt(64)
        }
        __syncwarp();
        // softmax
        float mx = -1e30f;
        for (int kb = lane; kb < Pp; kb += 32) mx = fmaxf(mx, ps[w * 200 + kb]);
        #pragma unroll
        for (int o = 16; o; o >>= 1) mx = fmaxf(mx, __shfl_xor_sync(0xffffffffu, mx, o));
        float sum = 0.f;
        for (int kb = lane; kb < Pp; kb += 32) {
            float e = __expf(ps[w * 200 + kb] - mx);
            ps[w * 200 + kb] = e;
            sum += e;
        }
        #pragma unroll
        for (int o = 16; o; o >>= 1) sum += __shfl_xor_sync(0xffffffffu, sum, o);
        float rinv = 1.0f / sum;
        __syncwarp();
        // AV: each lane owns 2 output dims
        float2 acc2 = make_float2(0.f, 0.f);
        for (int l = 0; l < Pp; l++) {
            float pl = ps[w * 200 + l];
            float2 vv = *(const float2*)(Vs + l * 68 + lane * 2);
            acc2.x += pl * vv.x;
            acc2.y += pl * vv.y;
        }
        float2 o2;
        o2.x = acc2.x * rinv;
        o2.y = acc2.y * rinv;
        ((float2*)(Ob + (size_t)p * Dd))[lane] = o2;
        __syncwarp();
    }
}

// ---------------- launch ----------------
extern "C" void kernel_launch(void* const* d_in, const int* in_sizes, int n_in,
                              void* d_out, int out_size) {
    const float* x    = (const float*)d_in[0];
    const float* Wq   = (const float*)d_in[1];
    const float* bq   = (const float*)d_in[2];
    const float* Wk   = (const float*)d_in[3];
    const float* bk   = (const float*)d_in[4];
    const float* Wv   = (const float*)d_in[5];
    const float* bv   = (const float*)d_in[6];
    const float* in_a = (const float*)d_in[7];
    const float* in_b = (const float*)d_in[8];
    const float* at_a = (const float*)d_in[9];
    const float* at_b = (const float*)d_in[10];
    const float* ou_a = (const float*)d_in[11];
    const float* ou_b = (const float*)d_in[12];
    const float* Wt   = (const float*)d_in[13];
    const float* bt   = (const float*)d_in[14];
    const float* pos  = (const float*)d_in[15];
    const float* W1   = (const float*)d_in[16];
    const float* b1   = (const float*)d_in[17];
    const float* W2   = (const float*)d_in[18];
    const float* b2   = (const float*)d_in[19];

    float *px2, *pq, *pk, *pv, *pav, *pxres, *ph;
    cudaGetSymbolAddress((void**)&px2,  g_x2);
    cudaGetSymbolAddress((void**)&pq,   g_q);
    cudaGetSymbolAddress((void**)&pk,   g_k);
    cudaGetSymbolAddress((void**)&pv,   g_v);
    cudaGetSymbolAddress((void**)&pav,  g_av);
    cudaGetSymbolAddress((void**)&pxres,g_xres);
    cudaGetSymbolAddress((void**)&ph,   g_h);

    cudaFuncSetAttribute(attn_k, cudaFuncAttributeMaxDynamicSharedMemorySize,
                         SMEM_ATTN_FLOATS * 4);

    // 1. btsum
    btsum_k<<<2, 256>>>(bt);
    // 2. LN(x) -> x2
    ln_k<<<M1, 256>>>(x, in_a, in_b, nullptr, px2, 1);
    // 3. QKV projections
    dim3 gqkv(Dd / 64, M1 / 64);
    gemm_k<<<gqkv, 256>>>(px2, Wq, bq, nullptr, pq, M1, Dd, Dd, 1.f, 0);
    gemm_k<<<gqkv, 256>>>(px2, Wk, bk, nullptr, pk, M1, Dd, Dd, 1.f, 0);
    gemm_k<<<gqkv, 256>>>(px2, Wv, bv, nullptr, pv, M1, Dd, Dd, 1.f, 0);
    // 4. fused attention -> av
    attn_k<<<Bq * Tt * Tt * Hh, 256, SMEM_ATTN_FLOATS * 4>>>();
    // 5. LN(av)+pos (in-place)
    ln_k<<<ROWS_AV, 256>>>(pav, at_a, at_b, pos, pav, POSMOD);
    // 6. tc contraction + gelu + residual -> xres
    dim3 gtc(Dd / 64, M1 / 64);
    gemm_tc_k<<<gtc, 256>>>(pav, Wt, x);
    // 7. LN(xres) -> x2
    ln_k<<<M1, 256>>>(pxres, ou_a, ou_b, nullptr, px2, 1);
    // 8. MLP1: h = gelu(x2 @ W1^T + b1)
    dim3 g1(2 * Dd / 64, M1 / 64);
    gemm_k<<<g1, 256>>>(px2, W1, b1, nullptr, ph, M1, 2 * Dd, Dd, 1.f, 1);
    // 9. MLP2: out = xres + gelu(h @ W2^T + b2)
    dim3 g2(Dd / 64, M1 / 64);
    gemm_k<<<g2, 256>>>(ph, W2, b2, pxres, (float*)d_out, M1, Dd, 2 * Dd, 1.f, 1);
}

// round 2
// speedup vs baseline: 1.7052x; 1.7052x over previous
#include <cuda_runtime.h>
#include <math.h>

#define Bq 4
#define Tt 12
#define Pp 196
#define Dd 512
#define Hh 8
#define DHd 64
#define EPSV 1e-6f

#define M1 (Bq*Tt*Pp)            // 9408
#define ROWS_AV (Bq*Tt*Tt*Pp)    // 112896
#define POSMOD (Tt*Tt*Pp)        // 28224

// ---------------- scratch (device globals; no allocations allowed) ----------
__device__ float g_x2[M1*Dd];
__device__ float g_q [M1*Dd];
__device__ float g_k [M1*Dd];
__device__ float g_v [M1*Dd];
__device__ float g_av[(size_t)ROWS_AV*Dd];
__device__ float g_xres[M1*Dd];
__device__ float g_h [M1*2*Dd];
__device__ float g_btsum[Dd];

// ---------------- helpers ----------------
__device__ __forceinline__ float gelu_exact(float x) {
    return 0.5f * x * (1.0f + erff(x * 0.70710678118654752f));
}

// ---------------- bt sum: btsum[e] = sum_u bt[u,e] ----------------
__global__ void btsum_k(const float* __restrict__ bt) {
    int e = blockIdx.x * blockDim.x + threadIdx.x;
    if (e < Dd) {
        float s = 0.f;
        #pragma unroll
        for (int u = 0; u < Tt; u++) s += bt[u * Dd + e];
        g_btsum[e] = s;
    }
}

// ---------------- LayerNorm (ddof=1, (sd+eps) denom), optional +pos --------
__global__ void ln_k(const float* __restrict__ in,
                     const float* __restrict__ al,
                     const float* __restrict__ be,
                     const float* __restrict__ pos,
                     float* __restrict__ out,
                     int posmod) {
    int row = blockIdx.x;
    int tid = threadIdx.x;
    const float2* rin = (const float2*)(in + (size_t)row * Dd);
    float2 v = rin[tid];
    float s  = v.x + v.y;
    float sq = v.x * v.x + v.y * v.y;
    #pragma unroll
    for (int o = 16; o; o >>= 1) {
        s  += __shfl_xor_sync(0xffffffffu, s,  o);
        sq += __shfl_xor_sync(0xffffffffu, sq, o);
    }
    __shared__ float ss[8], ssq[8];
    int w = tid >> 5;
    if ((tid & 31) == 0) { ss[w] = s; ssq[w] = sq; }
    __syncthreads();
    s = 0.f; sq = 0.f;
    #pragma unroll
    for (int i = 0; i < 8; i++) { s += ss[i]; sq += ssq[i]; }
    float mu  = s * (1.0f / Dd);
    float var = (sq - (float)Dd * mu * mu) * (1.0f / (Dd - 1));
    float inv = 1.0f / (sqrtf(fmaxf(var, 0.f)) + EPSV);

    float2 a = ((const float2*)al)[tid];
    float2 b = ((const float2*)be)[tid];
    float2 o;
    o.x = a.x * (v.x - mu) * inv + b.x;
    o.y = a.y * (v.y - mu) * inv + b.y;
    if (pos) {
        const float2* pr = (const float2*)(pos + (size_t)(row % posmod) * Dd);
        float2 p = pr[tid];
        o.x += p.x; o.y += p.y;
    }
    ((float2*)(out + (size_t)row * Dd))[tid] = o;
}

// ---------------- generic GEMM: C[m,n] = epi(scale*sum_k A[m,k]*B[n,k] + bias[n])
// A: [M,K] rm, B: [N,K] rm. 64x64 tile, BK=16, 256 threads, 4x4/thread.
// Vectorized: LDS.128 fragments, register prefetch of next k-tile.
__global__ void gemm_k(const float* __restrict__ A,
                       const float* __restrict__ Bm,
                       const float* __restrict__ bias,
                       const float* __restrict__ res,
                       float* __restrict__ C,
                       int M, int N, int K, float scale, int act) {
    __shared__ float As[16][68];
    __shared__ float Bs[16][68];
    int tid = threadIdx.x;
    int tx = tid & 15, ty = tid >> 4;
    int bm = blockIdx.y * 64, bn = blockIdx.x * 64;
    int lm = tid >> 2;          // 0..63
    int lk = (tid & 3) * 4;     // 0,4,8,12
    const float* Ap = A  + (size_t)(bm + lm) * K + lk;
    const float* Bp = Bm + (size_t)(bn + lm) * K + lk;
    float4 a4 = *(const float4*)Ap;
    float4 b4 = *(const float4*)Bp;
    float acc[4][4] = {};
    for (int k0 = 16; k0 <= K; k0 += 16) {
        As[lk+0][lm] = a4.x; As[lk+1][lm] = a4.y; As[lk+2][lm] = a4.z; As[lk+3][lm] = a4.w;
        Bs[lk+0][lm] = b4.x; Bs[lk+1][lm] = b4.y; Bs[lk+2][lm] = b4.z; Bs[lk+3][lm] = b4.w;
        __syncthreads();
        if (k0 < K) {
            a4 = *(const float4*)(Ap + k0);
            b4 = *(const float4*)(Bp + k0);
        }
        #pragma unroll
        for (int kk = 0; kk < 16; kk++) {
            float4 av4 = *(const float4*)&As[kk][ty * 4];
            float4 bv4 = *(const float4*)&Bs[kk][tx * 4];
            float a_[4] = {av4.x, av4.y, av4.z, av4.w};
            float b_[4] = {bv4.x, bv4.y, bv4.z, bv4.w};
            #pragma unroll
            for (int i = 0; i < 4; i++)
                #pragma unroll
                for (int j = 0; j < 4; j++)
                    acc[i][j] += a_[i] * b_[j];
        }
        __syncthreads();
    }
    float4 bia = *(const float4*)&bias[bn + tx * 4];
    float bb[4] = {bia.x, bia.y, bia.z, bia.w};
    #pragma unroll
    for (int i = 0; i < 4; i++) {
        int m = bm + ty * 4 + i;
        float v[4];
        #pragma unroll
        for (int j = 0; j < 4; j++) {
            v[j] = acc[i][j] * scale + bb[j];
            if (act) v[j] = gelu_exact(v[j]);
        }
        size_t off = (size_t)m * N + bn + tx * 4;
        if (res) {
            float4 r = *(const float4*)&res[off];
            v[0] += r.x; v[1] += r.y; v[2] += r.z; v[3] += r.w;
        }
        float4 o4 = make_float4(v[0], v[1], v[2], v[3]);
        *(float4*)&C[off] = o4;
    }
}

// ---------------- tc GEMM: M=9408, N=512, K=6144 (k = u*512+d) -------------
__global__ void gemm_tc_k(const float* __restrict__ Y,
                          const float* __restrict__ Wt,
                          const float* __restrict__ xin) {
    const int K = Tt * Dd;     // 6144
    __shared__ float As[16][68];
    __shared__ float Bs[16][68];
    int tid = threadIdx.x;
    int tx = tid & 15, ty = tid >> 4;
    int bm = blockIdx.y * 64, bn = blockIdx.x * 64;
    int lm = tid >> 2;
    int lk = (tid & 3) * 4;
    // per-thread A row base
    int m_ld = bm + lm;
    int b_ = m_ld / (Tt * Pp);
    int r_ = m_ld % (Tt * Pp);
    int t_ = r_ / Pp;
    int p_ = r_ % Pp;
    size_t rowbase = ((size_t)(b_ * (Tt * Tt) + t_ * Tt)) * (Pp * Dd) + (size_t)p_ * Dd + lk;
    size_t brow = (size_t)(bn + lm) * Dd + lk;

    auto lda = [&](int k0) -> float4 {
        int u = k0 >> 9, db = k0 & 511;
        return *(const float4*)&Y[rowbase + (size_t)u * (Pp * Dd) + db];
    };
    auto ldb = [&](int k0) -> float4 {
        int u = k0 >> 9, db = k0 & 511;
        return *(const float4*)&Wt[(size_t)u * (Dd * Dd) + brow - lk + db + lk];
    };

    float4 a4 = lda(0);
    float4 b4 = ldb(0);
    float acc[4][4] = {};
    for (int k0 = 16; k0 <= K; k0 += 16) {
        As[lk+0][lm] = a4.x; As[lk+1][lm] = a4.y; As[lk+2][lm] = a4.z; As[lk+3][lm] = a4.w;
        Bs[lk+0][lm] = b4.x; Bs[lk+1][lm] = b4.y; Bs[lk+2][lm] = b4.z; Bs[lk+3][lm] = b4.w;
        __syncthreads();
        if (k0 < K) {
            a4 = lda(k0);
            b4 = ldb(k0);
        }
        #pragma unroll
        for (int kk = 0; kk < 16; kk++) {
            float4 av4 = *(const float4*)&As[kk][ty * 4];
            float4 bv4 = *(const float4*)&Bs[kk][tx * 4];
            float a_[4] = {av4.x, av4.y, av4.z, av4.w};
            float b_[4] = {bv4.x, bv4.y, bv4.z, bv4.w};
            #pragma unroll
            for (int i = 0; i < 4; i++)
                #pragma unroll
                for (int j = 0; j < 4; j++)
                    acc[i][j] += a_[i] * b_[j];
        }
        __syncthreads();
    }
    float4 bts = *(const float4*)&g_btsum[bn + tx * 4];
    float bb[4] = {bts.x, bts.y, bts.z, bts.w};
    #pragma unroll
    for (int i = 0; i < 4; i++) {
        int m = bm + ty * 4 + i;
        size_t off = (size_t)m * Dd + bn + tx * 4;
        float4 xr = *(const float4*)&xin[off];
        float xi[4] = {xr.x, xr.y, xr.z, xr.w};
        float v[4];
        #pragma unroll
        for (int j = 0; j < 4; j++)
            v[j] = xi[j] + gelu_exact(acc[i][j] * (1.0f / Tt) + bb[j]);
        float4 o4 = make_float4(v[0], v[1], v[2], v[3]);
        *(float4*)&g_xres[off] = o4;
    }
}

// ---------------- fused attention: one block per (b,t,u,h) ----------------
// Ks padded to 224 rows (zero rows 196..223 so kl-loop is branch-free).
// Each warp processes 4 queries at a time: K/V smem tiles read once per 4 q.
#define KROWS 224
#define ATT_SM_FLOATS (KROWS*68 + Pp*68 + 8*4*68 + 8*4*200)
__global__ void attn_k() {
    int bid = blockIdx.x;
    int h = bid & 7;
    int u = (bid >> 3) % Tt;
    int t = (bid / (Hh * Tt)) % Tt;
    int b = bid / (Hh * Tt * Tt);

    extern __shared__ float sm[];
    float* Ks = sm;                       // [224][68]
    float* Vs = Ks + KROWS * 68;          // [196][68]
    float* qs = Vs + Pp * 68;             // [8][4][68]
    float* ps = qs + 8 * 4 * 68;          // [8][4][200]

    int tid  = threadIdx.x;  // 256
    int w    = tid >> 5;
    int lane = tid & 31;

    const float* Kb = g_k + ((size_t)(b * Tt + u) * Pp) * Dd + h * DHd;
    const float* Vb = g_v + ((size_t)(b * Tt + u) * Pp) * Dd + h * DHd;
    const float* Qb = g_q + ((size_t)(b * Tt + t) * Pp) * Dd + h * DHd;
    float*       Ob = g_av + ((size_t)((b * Tt + t) * Tt + u) * Pp) * Dd + h * DHd;

    // load K (zero-padded to 224 rows) and V
    for (int idx = tid; idx < KROWS * 16; idx += 256) {
        int l = idx >> 4, c = (idx & 15) * 4;
        float4 kv = make_float4(0.f, 0.f, 0.f, 0.f);
        if (l < Pp) {
            kv = *(const float4*)&Kb[(size_t)l * Dd + c];
            *(float4*)&Vs[l * 68 + c] = *(const float4*)&Vb[(size_t)l * Dd + c];
        }
        *(float4*)&Ks[l * 68 + c] = kv;
    }
    __syncthreads();

    float* pw = ps + w * 4 * 200;
    float* qw = qs + w * 4 * 68;

    for (int g = w; g < 49; g += 8) {
        int p0 = g * 4;
        // load 4 q rows
        for (int r = lane; r < 64; r += 32) {
            int j = r >> 4, c = (r & 15) * 4;
            *(float4*)&qw[j * 68 + c] = *(const float4*)&Qb[(size_t)(p0 + j) * Dd + c];
        }
        __syncwarp();

        // scores: acc[j][kl], kb = kl*32+lane
        float acc[4][7];
        #pragma unroll
        for (int j = 0; j < 4; j++)
            #pragma unroll
            for (int kl = 0; kl < 7; kl++) acc[j][kl] = 0.f;

        #pragma unroll
        for (int i = 0; i < 16; i++) {
            float4 q0 = *(const float4*)&qw[0 * 68 + i * 4];
            float4 q1 = *(const float4*)&qw[1 * 68 + i * 4];
            float4 q2 = *(const float4*)&qw[2 * 68 + i * 4];
            float4 q3 = *(const float4*)&qw[3 * 68 + i * 4];
            #pragma unroll
            for (int kl = 0; kl < 7; kl++) {
                float4 kv = *(const float4*)&Ks[(kl * 32 + lane) * 68 + i * 4];
                acc[0][kl] += q0.x*kv.x + q0.y*kv.y + q0.z*kv.z + q0.w*kv.w;
                acc[1][kl] += q1.x*kv.x + q1.y*kv.y + q1.z*kv.z + q1.w*kv.w;
                acc[2][kl] += q2.x*kv.x + q2.y*kv.y + q2.z*kv.z + q2.w*kv.w;
                acc[3][kl] += q3.x*kv.x + q3.y*kv.y + q3.z*kv.z + q3.w*kv.w;
            }
        }

        // scale; mark padded kb as -inf
        #pragma unroll
        for (int j = 0; j < 4; j++)
            #pragma unroll
            for (int kl = 0; kl < 7; kl++) {
                int kb = kl * 32 + lane;
                acc[j][kl] = (kb < Pp) ? acc[j][kl] * 0.125f : -1e30f;
            }

        // softmax per j (registers + shfl)
        float rinv[4];
        #pragma unroll
        for (int j = 0; j < 4; j++) {
            float mx = -1e30f;
            #pragma unroll
            for (int kl = 0; kl < 7; kl++) mx = fmaxf(mx, acc[j][kl]);
            #pragma unroll
            for (int o = 16; o; o >>= 1) mx = fmaxf(mx, __shfl_xor_sync(0xffffffffu, mx, o));
            float sum = 0.f;
            #pragma unroll
            for (int kl = 0; kl < 7; kl++) {
                int kb = kl * 32 + lane;
                float e = __expf(acc[j][kl] - mx);
                if (kb < Pp) { pw[j * 200 + kb] = e; sum += e; }
            }
            #pragma unroll
            for (int o = 16; o; o >>= 1) sum += __shfl_xor_sync(0xffffffffu, sum, o);
            rinv[j] = 1.0f / sum;
        }
        __syncwarp();

        // AV: lanes split (s = l parity), 4 dims per lane
        int s = lane >> 4;
        int r4 = (lane & 15) * 4;
        float4 o0 = make_float4(0,0,0,0), o1 = o0, o2 = o0, o3 = o0;
        for (int li = 0; li < Pp / 2; li++) {
            int l = 2 * li + s;
            float4 vv = *(const float4*)&Vs[l * 68 + r4];
            float pj0 = pw[0 * 200 + l];
            float pj1 = pw[1 * 200 + l];
            float pj2 = pw[2 * 200 + l];
            float pj3 = pw[3 * 200 + l];
            o0.x += pj0*vv.x; o0.y += pj0*vv.y; o0.z += pj0*vv.z; o0.w += pj0*vv.w;
            o1.x += pj1*vv.x; o1.y += pj1*vv.y; o1.z += pj1*vv.z; o1.w += pj1*vv.w;
            o2.x += pj2*vv.x; o2.y += pj2*vv.y; o2.z += pj2*vv.z; o2.w += pj2*vv.w;
            o3.x += pj3*vv.x; o3.y += pj3*vv.y; o3.z += pj3*vv.z; o3.w += pj3*vv.w;
        }
        // combine even/odd halves
        #pragma unroll
        for (int c = 0; c < 4; c++) {
            ((float*)&o0)[c] += __shfl_xor_sync(0xffffffffu, ((float*)&o0)[c], 16);
            ((float*)&o1)[c] += __shfl_xor_sync(0xffffffffu, ((float*)&o1)[c], 16);
            ((float*)&o2)[c] += __shfl_xor_sync(0xffffffffu, ((float*)&o2)[c], 16);
            ((float*)&o3)[c] += __shfl_xor_sync(0xffffffffu, ((float*)&o3)[c], 16);
        }
        if (lane < 16) {
            float4 w0 = make_float4(o0.x*rinv[0], o0.y*rinv[0], o0.z*rinv[0], o0.w*rinv[0]);
            float4 w1 = make_float4(o1.x*rinv[1], o1.y*rinv[1], o1.z*rinv[1], o1.w*rinv[1]);
            float4 w2 = make_float4(o2.x*rinv[2], o2.y*rinv[2], o2.z*rinv[2], o2.w*rinv[2]);
            float4 w3 = make_float4(o3.x*rinv[3], o3.y*rinv[3], o3.z*rinv[3], o3.w*rinv[3]);
            *(float4*)&Ob[(size_t)(p0+0) * Dd + r4] = w0;
            *(float4*)&Ob[(size_t)(p0+1) * Dd + r4] = w1;
            *(float4*)&Ob[(size_t)(p0+2) * Dd + r4] = w2;
            *(float4*)&Ob[(size_t)(p0+3) * Dd + r4] = w3;
        }
        __syncwarp();
    }
}

// ---------------- launch ----------------
extern "C" void kernel_launch(void* const* d_in, const int* in_sizes, int n_in,
                              void* d_out, int out_size) {
    const float* x    = (const float*)d_in[0];
    const float* Wq   = (const float*)d_in[1];
    const float* bq   = (const float*)d_in[2];
    const float* Wk   = (const float*)d_in[3];
    const float* bk   = (const float*)d_in[4];
    const float* Wv   = (const float*)d_in[5];
    const float* bv   = (const float*)d_in[6];
    const float* in_a = (const float*)d_in[7];
    const float* in_b = (const float*)d_in[8];
    const float* at_a = (const float*)d_in[9];
    const float* at_b = (const float*)d_in[10];
    const float* ou_a = (const float*)d_in[11];
    const float* ou_b = (const float*)d_in[12];
    const float* Wt   = (const float*)d_in[13];
    const float* bt   = (const float*)d_in[14];
    const float* pos  = (const float*)d_in[15];
    const float* W1   = (const float*)d_in[16];
    const float* b1   = (const float*)d_in[17];
    const float* W2   = (const float*)d_in[18];
    const float* b2   = (const float*)d_in[19];

    float *px2, *pq, *pk, *pv, *pav, *pxres, *ph;
    cudaGetSymbolAddress((void**)&px2,  g_x2);
    cudaGetSymbolAddress((void**)&pq,   g_q);
    cudaGetSymbolAddress((void**)&pk,   g_k);
    cudaGetSymbolAddress((void**)&pv,   g_v);
    cudaGetSymbolAddress((void**)&pav,  g_av);
    cudaGetSymbolAddress((void**)&pxres,g_xres);
    cudaGetSymbolAddress((void**)&ph,   g_h);

    cudaFuncSetAttribute(attn_k, cudaFuncAttributeMaxDynamicSharedMemorySize,
                         ATT_SM_FLOATS * 4);

    btsum_k<<<2, 256>>>(bt);
    ln_k<<<M1, 256>>>(x, in_a, in_b, nullptr, px2, 1);

    dim3 gqkv(Dd / 64, M1 / 64);
    gemm_k<<<gqkv, 256>>>(px2, Wq, bq, nullptr, pq, M1, Dd, Dd, 1.f, 0);
    gemm_k<<<gqkv, 256>>>(px2, Wk, bk, nullptr, pk, M1, Dd, Dd, 1.f, 0);
    gemm_k<<<gqkv, 256>>>(px2, Wv, bv, nullptr, pv, M1, Dd, Dd, 1.f, 0);

    attn_k<<<Bq * Tt * Tt * Hh, 256, ATT_SM_FLOATS * 4>>>();

    ln_k<<<ROWS_AV, 256>>>(pav, at_a, at_b, pos, pav, POSMOD);

    dim3 gtc(Dd / 64, M1 / 64);
    gemm_tc_k<<<gtc, 256>>>(pav, Wt, x);

    ln_k<<<M1, 256>>>(pxres, ou_a, ou_b, nullptr, px2, 1);

    dim3 g1(2 * Dd / 64, M1 / 64);
    gemm_k<<<g1, 256>>>(px2, W1, b1, nullptr, ph, M1, 2 * Dd, Dd, 1.f, 1);
    dim3 g2(Dd / 64, M1 / 64);
    gemm_k<<<g2, 256>>>(ph, W2, b2, pxres, (float*)d_out, M1, Dd, 2 * Dd, 1.f, 1);
}

// round 4
// speedup vs baseline: 2.5045x; 1.4688x over previous
#include <cuda_runtime.h>
#include <cuda_bf16.h>
#include <math.h>
#include <stdint.h>

#define Bq 4
#define Tt 12
#define Pp 196
#define Dd 512
#define Hh 8
#define DHd 64
#define EPSV 1e-6f

#define M1 (Bq*Tt*Pp)            // 9408
#define ROWS_AV (Bq*Tt*Tt*Pp)    // 112896
#define POSMOD (Tt*Tt*Pp)        // 28224

// weight offsets in converted buffer
#define OQ 0
#define OKo 262144
#define OV  524288
#define OT  786432
#define O1  3932160
#define O2  4456448
#define WTOT 4980736

// ---------------- scratch (device globals; no allocations allowed) ----------
__device__ float g_q [M1*Dd];
__device__ float g_k [M1*Dd];
__device__ float g_v [M1*Dd];
__device__ float g_av[(size_t)ROWS_AV*Dd];
__device__ float g_xres[M1*Dd];
__device__ float g_btsum[Dd];
__device__ __nv_bfloat16 g_x2h[M1*Dd],  g_x2l[M1*Dd];
__device__ __nv_bfloat16 g_yh[(size_t)ROWS_AV*Dd], g_yl[(size_t)ROWS_AV*Dd];
__device__ __nv_bfloat16 g_hh[M1*2*Dd], g_hl[M1*2*Dd];
__device__ __nv_bfloat16 w_hi[WTOT], w_lo[WTOT];

// ---------------- helpers ----------------
__device__ __forceinline__ float gelu_exact(float x) {
    return 0.5f * x * (1.0f + erff(x * 0.70710678118654752f));
}
__device__ __forceinline__ uint32_t smem_u32(const void* p) {
    uint32_t a;
    asm("{ .reg .u64 t; cvta.to.shared.u64 t, %1; cvt.u32.u64 %0, t; }" : "=r"(a) : "l"(p));
    return a;
}
__device__ __forceinline__ void ldsm4(uint32_t* r, uint32_t a) {
    asm volatile("ldmatrix.sync.aligned.m8n8.x4.shared.b16 {%0,%1,%2,%3}, [%4];"
                 : "=r"(r[0]), "=r"(r[1]), "=r"(r[2]), "=r"(r[3]) : "r"(a));
}
__device__ __forceinline__ void mma_bf16(float* c, const uint32_t* a, uint32_t b0, uint32_t b1) {
    asm volatile(
        "mma.sync.aligned.m16n8k16.row.col.f32.bf16.bf16.f32 "
        "{%0,%1,%2,%3}, {%4,%5,%6,%7}, {%8,%9}, {%0,%1,%2,%3};"
        : "+f"(c[0]), "+f"(c[1]), "+f"(c[2]), "+f"(c[3])
        : "r"(a[0]), "r"(a[1]), "r"(a[2]), "r"(a[3]), "r"(b0), "r"(b1));
}
__device__ __forceinline__ void cpa16(uint32_t s, const void* g) {
    asm volatile("cp.async.cg.shared.global [%0], [%1], 16;" :: "r"(s), "l"(g));
}
#define CPA_COMMIT() asm volatile("cp.async.commit_group;" ::: "memory")
#define CPA_WAIT(n)  asm volatile("cp.async.wait_group %0;" :: "n"(n) : "memory")

// ---------------- bt sum ----------------
__global__ void btsum_k(const float* __restrict__ bt) {
    int e = blockIdx.x * blockDim.x + threadIdx.x;
    if (e < Dd) {
        float s = 0.f;
        #pragma unroll
        for (int u = 0; u < Tt; u++) s += bt[u * Dd + e];
        g_btsum[e] = s;
    }
}

// ---------------- weight fp32 -> bf16 hi/lo ----------------
__global__ void wcvt_k(const float* __restrict__ src, __nv_bfloat16* __restrict__ hi,
                       __nv_bfloat16* __restrict__ lo, int n) {
    int i = blockIdx.x * blockDim.x + threadIdx.x;
    if (i < n) {
        float v = src[i];
        __nv_bfloat16 h = __float2bfloat16(v);
        hi[i] = h;
        lo[i] = __float2bfloat16(v - __bfloat162float(h));
    }
}

// ---------------- LayerNorm -> bf16 hi/lo (optional +pos) ----------------
__global__ void ln_bf_k(const float* __restrict__ in,
                        const float* __restrict__ al,
                        const float* __restrict__ be,
                        const float* __restrict__ pos,
                        __nv_bfloat16* __restrict__ oh,
                        __nv_bfloat16* __restrict__ ol,
                        int posmod) {
    int row = blockIdx.x;
    int tid = threadIdx.x;
    const float2* rin = (const float2*)(in + (size_t)row * Dd);
    float2 v = rin[tid];
    float s  = v.x + v.y;
    float sq = v.x * v.x + v.y * v.y;
    #pragma unroll
    for (int o = 16; o; o >>= 1) {
        s  += __shfl_xor_sync(0xffffffffu, s,  o);
        sq += __shfl_xor_sync(0xffffffffu, sq, o);
    }
    __shared__ float ss[8], ssq[8];
    int w = tid >> 5;
    if ((tid & 31) == 0) { ss[w] = s; ssq[w] = sq; }
    __syncthreads();
    s = 0.f; sq = 0.f;
    #pragma unroll
    for (int i = 0; i < 8; i++) { s += ss[i]; sq += ssq[i]; }
    float mu  = s * (1.0f / Dd);
    float var = (sq - (float)Dd * mu * mu) * (1.0f / (Dd - 1));
    float inv = 1.0f / (sqrtf(fmaxf(var, 0.f)) + EPSV);

    float2 a = ((const float2*)al)[tid];
    float2 b = ((const float2*)be)[tid];
    float ox = a.x * (v.x - mu) * inv + b.x;
    float oy = a.y * (v.y - mu) * inv + b.y;
    if (pos) {
        const float2* pr = (const float2*)(pos + (size_t)(row % posmod) * Dd);
        float2 p = pr[tid];
        ox += p.x; oy += p.y;
    }
    __nv_bfloat16 hx = __float2bfloat16(ox);
    __nv_bfloat16 hy = __float2bfloat16(oy);
    __nv_bfloat16 lx = __float2bfloat16(ox - __bfloat162float(hx));
    __nv_bfloat16 ly = __float2bfloat16(oy - __bfloat162float(hy));
    ((__nv_bfloat162*)(oh + (size_t)row * Dd))[tid] = __nv_bfloat162(hx, hy);
    ((__nv_bfloat162*)(ol + (size_t)row * Dd))[tid] = __nv_bfloat162(lx, ly);
}

// ================= mma.sync bf16x3 GEMM ======================
// C[m,n] = epilogue( sum_k A[m,k]*B[n,k] ), A hi/lo, B hi/lo bf16.
// Block 128x128, 8 warps (2m x 4n), warp tile 64x32, K-chunk 64, double buffer.
// modes: 0: Cf = acc + bias
//        1 (tc): Cf = res + gelu(acc/12 + bias); A is [b,t,u,p,d], B per-u
//        2: Chi/Clo = split(gelu(acc + bias))
//        3: Cf = res + gelu(acc + bias)
#define LDSE 72
#define TILE_B (128*LDSE*2)       // 18432
#define STAGE_B (4*TILE_B)        // 73728
#define GM_SMEM (2*STAGE_B)       // 147456

__global__ void __launch_bounds__(256, 1) gemm_mma_k(
    const __nv_bfloat16* __restrict__ Ahi, const __nv_bfloat16* __restrict__ Alo,
    const __nv_bfloat16* __restrict__ Bhi, const __nv_bfloat16* __restrict__ Blo,
    const float* __restrict__ bias, const float* __restrict__ res,
    float* __restrict__ Cf, __nv_bfloat16* __restrict__ Chi, __nv_bfloat16* __restrict__ Clo,
    int M, int N, int K, int mode)
{
    extern __shared__ char smc[];
    int tid = threadIdx.x;
    int wid = tid >> 5, lane = tid & 31;
    int bm = blockIdx.y * 128, bn = blockIdx.x * 128;
    int wm = (wid >> 2) * 64;       // 0 or 64
    int wn = (wid & 3) * 32;        // 0,32,64,96

    // ---- load indexing
    int lrow = tid >> 1;            // 0..127
    int lhalf = tid & 1;            // 0/1
    int am = min(bm + lrow, M - 1);
    size_t abase;
    if (mode == 1) {
        int b_ = am / (Tt * Pp), r_ = am % (Tt * Pp);
        int t_ = r_ / Pp, p_ = r_ % Pp;
        abase = ((size_t)(b_ * (Tt * Tt) + t_ * Tt) * Pp + p_) * Dd;
    } else {
        abase = (size_t)am * K;
    }
    int brow = bn + lrow;
    uint32_t smrow = lrow * (LDSE * 2);

    int NC = K / 64;

    auto load_stage = [&](int buf, int c) {
        size_t aoff, boff;
        if (mode == 1) {
            int u = c >> 3, d0 = (c & 7) * 64;
            aoff = abase + (size_t)u * (Pp * Dd) + d0;
            boff = (size_t)u * (Dd * Dd) + (size_t)brow * Dd + d0;
        } else {
            aoff = abase + c * 64;
            boff = (size_t)brow * K + c * 64;
        }
        uint32_t sb = smem_u32(smc) + buf * STAGE_B + smrow;
        #pragma unroll
        for (int i = 0; i < 4; i++) {
            int colk = lhalf * 32 + i * 8;
            uint32_t so = sb + colk * 2;
            cpa16(so,              Ahi + aoff + colk);
            cpa16(so + TILE_B,     Alo + aoff + colk);
            cpa16(so + 2*TILE_B,   Bhi + boff + colk);
            cpa16(so + 3*TILE_B,   Blo + boff + colk);
        }
    };

    // ---- ldmatrix per-lane address pieces
    int sel = lane >> 3, lr = lane & 7;
    int a_m = wm + (sel & 1) * 8 + lr;
    int a_k = (sel >> 1) * 8;
    int b_n = wn + (sel >> 1) * 8 + lr;
    int b_k = (sel & 1) * 8;
    uint32_t smb = smem_u32(smc);
    uint32_t aoffB = (a_m * LDSE + a_k) * 2;
    uint32_t boffB = (b_n * LDSE + b_k) * 2;

    float acc[4][4][4] = {};

    load_stage(0, 0);
    CPA_COMMIT();

    for (int c = 0; c < NC; c++) {
        int buf = c & 1;
        if (c + 1 < NC) {
            load_stage(buf ^ 1, c + 1);
            CPA_COMMIT();
            CPA_WAIT(1);
        } else {
            CPA_WAIT(0);
        }
        __syncthreads();

        uint32_t base = smb + buf * STAGE_B;
        uint32_t aHb = base + aoffB;
        uint32_t aLb = aHb + TILE_B;
        uint32_t bHb = base + 2*TILE_B + boffB;
        uint32_t bLb = bHb + TILE_B;

        #pragma unroll
        for (int kk = 0; kk < 4; kk++) {
            uint32_t ko = kk * 32;  // 16 bf16 = 32 bytes
            uint32_t aH[4][4], aL[4][4], bH[2][4], bL[2][4];
            #pragma unroll
            for (int mt = 0; mt < 4; mt++) {
                ldsm4(aH[mt], aHb + mt * (16 * LDSE * 2) + ko);
                ldsm4(aL[mt], aLb + mt * (16 * LDSE * 2) + ko);
            }
            #pragma unroll
            for (int nt2 = 0; nt2 < 2; nt2++) {
                ldsm4(bH[nt2], bHb + nt2 * (16 * LDSE * 2) + ko);
                ldsm4(bL[nt2], bLb + nt2 * (16 * LDSE * 2) + ko);
            }
            #pragma unroll
            for (int mt = 0; mt < 4; mt++) {
                #pragma unroll
                for (int nt = 0; nt < 4; nt++) {
                    int s2 = nt >> 1, pp = (nt & 1) * 2;
                    mma_bf16(acc[mt][nt], aH[mt], bH[s2][pp], bH[s2][pp+1]);
                    mma_bf16(acc[mt][nt], aH[mt], bL[s2][pp], bL[s2][pp+1]);
                    mma_bf16(acc[mt][nt], aL[mt], bH[s2][pp], bH[s2][pp+1]);
                }
            }
        }
        __syncthreads();
    }

    // ---- epilogue
    int qrow = lane >> 2;
    int qcol = (lane & 3) * 2;
    #pragma unroll
    for (int mt = 0; mt < 4; mt++) {
        #pragma unroll
        for (int nt = 0; nt < 4; nt++) {
            float* cc = acc[mt][nt];
            int n0 = bn + wn + nt * 8 + qcol;
            float b0 = bias[n0], b1 = bias[n0 + 1];
            #pragma unroll
            for (int hrow = 0; hrow < 2; hrow++) {
                int m = bm + wm + mt * 16 + qrow + hrow * 8;
                if (m >= M) continue;
                float a0 = cc[hrow * 2 + 0];
                float a1 = cc[hrow * 2 + 1];
                size_t off = (size_t)m * N + n0;
                float v0, v1;
                if (mode == 0) {
                    v0 = a0 + b0; v1 = a1 + b1;
                } else if (mode == 1) {
                    float2 r = *(const float2*)&res[off];
                    v0 = r.x + gelu_exact(a0 * (1.0f / Tt) + b0);
                    v1 = r.y + gelu_exact(a1 * (1.0f / Tt) + b1);
                } else if (mode == 3) {
                    float2 r = *(const float2*)&res[off];
                    v0 = r.x + gelu_exact(a0 + b0);
                    v1 = r.y + gelu_exact(a1 + b1);
                } else { // mode 2
                    float g0 = gelu_exact(a0 + b0);
                    float g1 = gelu_exact(a1 + b1);
                    __nv_bfloat16 h0 = __float2bfloat16(g0);
                    __nv_bfloat16 h1 = __float2bfloat16(g1);
                    __nv_bfloat16 l0 = __float2bfloat16(g0 - __bfloat162float(h0));
                    __nv_bfloat16 l1 = __float2bfloat16(g1 - __bfloat162float(h1));
                    *(__nv_bfloat162*)(Chi + off) = __nv_bfloat162(h0, h1);
                    *(__nv_bfloat162*)(Clo + off) = __nv_bfloat162(l0, l1);
                    continue;
                }
                *(float2*)&Cf[off] = make_float2(v0, v1);
            }
        }
    }
}

// ---------------- fused attention (unchanged, validated) -----------
#define KROWS 224
#define ATT_SM_FLOATS (KROWS*68 + Pp*68 + 8*4*68 + 8*4*200)
__global__ void attn_k() {
    int bid = blockIdx.x;
    int h = bid & 7;
    int u = (bid >> 3) % Tt;
    int t = (bid / (Hh * Tt)) % Tt;
    int b = bid / (Hh * Tt * Tt);

    extern __shared__ float sm[];
    float* Ks = sm;
    float* Vs = Ks + KROWS * 68;
    float* qs = Vs + Pp * 68;
    float* ps = qs + 8 * 4 * 68;

    int tid  = threadIdx.x;
    int w    = tid >> 5;
    int lane = tid & 31;

    const float* Kb = g_k + ((size_t)(b * Tt + u) * Pp) * Dd + h * DHd;
    const float* Vb = g_v + ((size_t)(b * Tt + u) * Pp) * Dd + h * DHd;
    const float* Qb = g_q + ((size_t)(b * Tt + t) * Pp) * Dd + h * DHd;
    float*       Ob = g_av + ((size_t)((b * Tt + t) * Tt + u) * Pp) * Dd + h * DHd;

    for (int idx = tid; idx < KROWS * 16; idx += 256) {
        int l = idx >> 4, c = (idx & 15) * 4;
        float4 kv = make_float4(0.f, 0.f, 0.f, 0.f);
        if (l < Pp) {
            kv = *(const float4*)&Kb[(size_t)l * Dd + c];
            *(float4*)&Vs[l * 68 + c] = *(const float4*)&Vb[(size_t)l * Dd + c];
        }
        *(float4*)&Ks[l * 68 + c] = kv;
    }
    __syncthreads();

    float* pw = ps + w * 4 * 200;
    float* qw = qs + w * 4 * 68;

    for (int g = w; g < 49; g += 8) {
        int p0 = g * 4;
        for (int r = lane; r < 64; r += 32) {
            int j = r >> 4, c = (r & 15) * 4;
            *(float4*)&qw[j * 68 + c] = *(const float4*)&Qb[(size_t)(p0 + j) * Dd + c];
        }
        __syncwarp();

        float acc[4][7];
        #pragma unroll
        for (int j = 0; j < 4; j++)
            #pragma unroll
            for (int kl = 0; kl < 7; kl++) acc[j][kl] = 0.f;

        #pragma unroll
        for (int i = 0; i < 16; i++) {
            float4 q0 = *(const float4*)&qw[0 * 68 + i * 4];
            float4 q1 = *(const float4*)&qw[1 * 68 + i * 4];
            float4 q2 = *(const float4*)&qw[2 * 68 + i * 4];
            float4 q3 = *(const float4*)&qw[3 * 68 + i * 4];
            #pragma unroll
            for (int kl = 0; kl < 7; kl++) {
                float4 kv = *(const float4*)&Ks[(kl * 32 + lane) * 68 + i * 4];
                acc[0][kl] += q0.x*kv.x + q0.y*kv.y + q0.z*kv.z + q0.w*kv.w;
                acc[1][kl] += q1.x*kv.x + q1.y*kv.y + q1.z*kv.z + q1.w*kv.w;
                acc[2][kl] += q2.x*kv.x + q2.y*kv.y + q2.z*kv.z + q2.w*kv.w;
                acc[3][kl] += q3.x*kv.x + q3.y*kv.y + q3.z*kv.z + q3.w*kv.w;
            }
        }

        #pragma unroll
        for (int j = 0; j < 4; j++)
            #pragma unroll
            for (int kl = 0; kl < 7; kl++) {
                int kb = kl * 32 + lane;
                acc[j][kl] = (kb < Pp) ? acc[j][kl] * 0.125f : -1e30f;
            }

        float rinv[4];
        #pragma unroll
        for (int j = 0; j < 4; j++) {
            float mx = -1e30f;
            #pragma unroll
            for (int kl = 0; kl < 7; kl++) mx = fmaxf(mx, acc[j][kl]);
            #pragma unroll
            for (int o = 16; o; o >>= 1) mx = fmaxf(mx, __shfl_xor_sync(0xffffffffu, mx, o));
            float sum = 0.f;
            #pragma unroll
            for (int kl = 0; kl < 7; kl++) {
                int kb = kl * 32 + lane;
                float e = __expf(acc[j][kl] - mx);
                if (kb < Pp) { pw[j * 200 + kb] = e; sum += e; }
            }
            #pragma unroll
            for (int o = 16; o; o >>= 1) sum += __shfl_xor_sync(0xffffffffu, sum, o);
            rinv[j] = 1.0f / sum;
        }
        __syncwarp();

        int s = lane >> 4;
        int r4 = (lane & 15) * 4;
        float4 o0 = make_float4(0,0,0,0), o1 = o0, o2 = o0, o3 = o0;
        for (int li = 0; li < Pp / 2; li++) {
            int l = 2 * li + s;
            float4 vv = *(const float4*)&Vs[l * 68 + r4];
            float pj0 = pw[0 * 200 + l];
            float pj1 = pw[1 * 200 + l];
            float pj2 = pw[2 * 200 + l];
            float pj3 = pw[3 * 200 + l];
            o0.x += pj0*vv.x; o0.y += pj0*vv.y; o0.z += pj0*vv.z; o0.w += pj0*vv.w;
            o1.x += pj1*vv.x; o1.y += pj1*vv.y; o1.z += pj1*vv.z; o1.w += pj1*vv.w;
            o2.x += pj2*vv.x; o2.y += pj2*vv.y; o2.z += pj2*vv.z; o2.w += pj2*vv.w;
            o3.x += pj3*vv.x; o3.y += pj3*vv.y; o3.z += pj3*vv.z; o3.w += pj3*vv.w;
        }
        #pragma unroll
        for (int c = 0; c < 4; c++) {
            ((float*)&o0)[c] += __shfl_xor_sync(0xffffffffu, ((float*)&o0)[c], 16);
            ((float*)&o1)[c] += __shfl_xor_sync(0xffffffffu, ((float*)&o1)[c], 16);
            ((float*)&o2)[c] += __shfl_xor_sync(0xffffffffu, ((float*)&o2)[c], 16);
            ((float*)&o3)[c] += __shfl_xor_sync(0xffffffffu, ((float*)&o3)[c], 16);
        }
        if (lane < 16) {
            float4 w0 = make_float4(o0.x*rinv[0], o0.y*rinv[0], o0.z*rinv[0], o0.w*rinv[0]);
            float4 w1 = make_float4(o1.x*rinv[1], o1.y*rinv[1], o1.z*rinv[1], o1.w*rinv[1]);
            float4 w2 = make_float4(o2.x*rinv[2], o2.y*rinv[2], o2.z*rinv[2], o2.w*rinv[2]);
            float4 w3 = make_float4(o3.x*rinv[3], o3.y*rinv[3], o3.z*rinv[3], o3.w*rinv[3]);
            *(float4*)&Ob[(size_t)(p0+0) * Dd + r4] = w0;
            *(float4*)&Ob[(size_t)(p0+1) * Dd + r4] = w1;
            *(float4*)&Ob[(size_t)(p0+2) * Dd + r4] = w2;
            *(float4*)&Ob[(size_t)(p0+3) * Dd + r4] = w3;
        }
        __syncwarp();
    }
}

// ---------------- launch ----------------
extern "C" void kernel_launch(void* const* d_in, const int* in_sizes, int n_in,
                              void* d_out, int out_size) {
    const float* x    = (const float*)d_in[0];
    const float* Wq   = (const float*)d_in[1];
    const float* bq   = (const float*)d_in[2];
    const float* Wk   = (const float*)d_in[3];
    const float* bk   = (const float*)d_in[4];
    const float* Wv   = (const float*)d_in[5];
    const float* bv   = (const float*)d_in[6];
    const float* in_a = (const float*)d_in[7];
    const float* in_b = (const float*)d_in[8];
    const float* at_a = (const float*)d_in[9];
    const float* at_b = (const float*)d_in[10];
    const float* ou_a = (const float*)d_in[11];
    const float* ou_b = (const float*)d_in[12];
    const float* Wt   = (const float*)d_in[13];
    const float* bt   = (const float*)d_in[14];
    const float* pos  = (const float*)d_in[15];
    const float* W1   = (const float*)d_in[16];
    const float* b1   = (const float*)d_in[17];
    const float* W2   = (const float*)d_in[18];
    const float* b2   = (const float*)d_in[19];

    float *pq, *pk, *pv, *pav, *pxres, *pbtsum;
    __nv_bfloat16 *px2h, *px2l, *pyh, *pyl, *phh, *phl, *pwh, *pwl;
    cudaGetSymbolAddress((void**)&pq,   g_q);
    cudaGetSymbolAddress((void**)&pk,   g_k);
    cudaGetSymbolAddress((void**)&pv,   g_v);
    cudaGetSymbolAddress((void**)&pav,  g_av);
    cudaGetSymbolAddress((void**)&pxres,g_xres);
    cudaGetSymbolAddress((void**)&pbtsum, g_btsum);
    cudaGetSymbolAddress((void**)&px2h, g_x2h);
    cudaGetSymbolAddress((void**)&px2l, g_x2l);
    cudaGetSymbolAddress((void**)&pyh,  g_yh);
    cudaGetSymbolAddress((void**)&pyl,  g_yl);
    cudaGetSymbolAddress((void**)&phh,  g_hh);
    cudaGetSymbolAddress((void**)&phl,  g_hl);
    cudaGetSymbolAddress((void**)&pwh,  w_hi);
    cudaGetSymbolAddress((void**)&pwl,  w_lo);

    cudaFuncSetAttribute(attn_k, cudaFuncAttributeMaxDynamicSharedMemorySize,
                         ATT_SM_FLOATS * 4);
    cudaFuncSetAttribute(gemm_mma_k, cudaFuncAttributeMaxDynamicSharedMemorySize,
                         GM_SMEM);

    // weight conversions
    wcvt_k<<<(262144 + 255) / 256, 256>>>(Wq, pwh + OQ,  pwl + OQ,  262144);
    wcvt_k<<<(262144 + 255) / 256, 256>>>(Wk, pwh + OKo, pwl + OKo, 262144);
    wcvt_k<<<(262144 + 255) / 256, 256>>>(Wv, pwh + OV,  pwl + OV,  262144);
    wcvt_k<<<(3145728 + 255) / 256, 256>>>(Wt, pwh + OT, pwl + OT, 3145728);
    wcvt_k<<<(524288 + 255) / 256, 256>>>(W1, pwh + O1,  pwl + O1,  524288);
    wcvt_k<<<(524288 + 255) / 256, 256>>>(W2, pwh + O2,  pwl + O2,  524288);
    btsum_k<<<2, 256>>>(bt);

    // LN(x) -> x2 hi/lo
    ln_bf_k<<<M1, 256>>>(x, in_a, in_b, nullptr, px2h, px2l, 1);

    // QKV projections (mode 0)
    dim3 gqkv(Dd / 128, (M1 + 127) / 128);
    gemm_mma_k<<<gqkv, 256, GM_SMEM>>>(px2h, px2l, pwh + OQ,  pwl + OQ,  bq, nullptr, pq, nullptr, nullptr, M1, Dd, Dd, 0);
    gemm_mma_k<<<gqkv, 256, GM_SMEM>>>(px2h, px2l, pwh + OKo, pwl + OKo, bk, nullptr, pk, nullptr, nullptr, M1, Dd, Dd, 0);
    gemm_mma_k<<<gqkv, 256, GM_SMEM>>>(px2h, px2l, pwh + OV,  pwl + OV,  bv, nullptr, pv, nullptr, nullptr, M1, Dd, Dd, 0);

    // attention
    attn_k<<<Bq * Tt * Tt * Hh, 256, ATT_SM_FLOATS * 4>>>();

    // LN(av)+pos -> y hi/lo
    ln_bf_k<<<ROWS_AV, 256>>>(pav, at_a, at_b, pos, pyh, pyl, POSMOD);

    // tc contraction (mode 1)
    gemm_mma_k<<<gqkv, 256, GM_SMEM>>>(pyh, pyl, pwh + OT, pwl + OT, pbtsum, x, pxres, nullptr, nullptr, M1, Dd, Tt * Dd, 1);

    // LN(xres) -> x2 hi/lo
    ln_bf_k<<<M1, 256>>>(pxres, ou_a, ou_b, nullptr, px2h, px2l, 1);

    // MLP1 (mode 2) -> h hi/lo
    dim3 g1(2 * Dd / 128, (M1 + 127) / 128);
    gemm_mma_k<<<g1, 256, GM_SMEM>>>(px2h, px2l, pwh + O1, pwl + O1, b1, nullptr, nullptr, phh, phl, M1, 2 * Dd, Dd, 2);

    // MLP2 (mode 3) -> d_out
    gemm_mma_k<<<gqkv, 256, GM_SMEM>>>(phh, phl, pwh + O2, pwl + O2, b2, pxres, (float*)d_out, nullptr, nullptr, M1, Dd, 2 * Dd, 3);
}

// round 5
// speedup vs baseline: 3.3641x; 1.3432x over previous
#include <cuda_runtime.h>
#include <cuda_bf16.h>
#include <math.h>
#include <stdint.h>

#define Bq 4
#define Tt 12
#define Pp 196
#define Dd 512
#define Hh 8
#define DHd 64
#define EPSV 1e-6f

#define M1 (Bq*Tt*Pp)            // 9408
#define ROWS_AV (Bq*Tt*Tt*Pp)    // 112896
#define POSMOD (Tt*Tt*Pp)        // 28224

// weight offsets in converted buffer
#define OQ 0
#define OKo 262144
#define OV  524288
#define OT  786432
#define O1  3932160
#define O2  4456448
#define WTOT 4980736

// ---------------- scratch ----------------
__device__ float g_av[(size_t)ROWS_AV*Dd];
__device__ float g_xres[M1*Dd];
__device__ float g_btsum[Dd];
__device__ __nv_bfloat16 g_x2h[M1*Dd],  g_x2l[M1*Dd];
__device__ __nv_bfloat16 g_qh[M1*Dd], g_ql[M1*Dd];
__device__ __nv_bfloat16 g_kh[M1*Dd], g_kl[M1*Dd];
__device__ __nv_bfloat16 g_vh[M1*Dd], g_vl[M1*Dd];
__device__ __nv_bfloat16 g_yh[(size_t)ROWS_AV*Dd], g_yl[(size_t)ROWS_AV*Dd];
__device__ __nv_bfloat16 g_hh[M1*2*Dd], g_hl[M1*2*Dd];
__device__ __nv_bfloat16 w_hi[WTOT], w_lo[WTOT];

// ---------------- helpers ----------------
__device__ __forceinline__ float gelu_exact(float x) {
    return 0.5f * x * (1.0f + erff(x * 0.70710678118654752f));
}
__device__ __forceinline__ uint32_t smem_u32(const void* p) {
    uint32_t a;
    asm("{ .reg .u64 t; cvta.to.shared.u64 t, %1; cvt.u32.u64 %0, t; }" : "=r"(a) : "l"(p));
    return a;
}
__device__ __forceinline__ void ldsm4(uint32_t* r, uint32_t a) {
    asm volatile("ldmatrix.sync.aligned.m8n8.x4.shared.b16 {%0,%1,%2,%3}, [%4];"
                 : "=r"(r[0]), "=r"(r[1]), "=r"(r[2]), "=r"(r[3]) : "r"(a));
}
__device__ __forceinline__ void mma_bf16(float* c, const uint32_t* a, uint32_t b0, uint32_t b1) {
    asm volatile(
        "mma.sync.aligned.m16n8k16.row.col.f32.bf16.bf16.f32 "
        "{%0,%1,%2,%3}, {%4,%5,%6,%7}, {%8,%9}, {%0,%1,%2,%3};"
        : "+f"(c[0]), "+f"(c[1]), "+f"(c[2]), "+f"(c[3])
        : "r"(a[0]), "r"(a[1]), "r"(a[2]), "r"(a[3]), "r"(b0), "r"(b1));
}
__device__ __forceinline__ void cpa16(uint32_t s, const void* g) {
    asm volatile("cp.async.cg.shared.global [%0], [%1], 16;" :: "r"(s), "l"(g));
}
#define CPA_COMMIT() asm volatile("cp.async.commit_group;" ::: "memory")
#define CPA_WAIT(n)  asm volatile("cp.async.wait_group %0;" :: "n"(n) : "memory")

__device__ __forceinline__ uint32_t pack_bf16(float a, float b) {
    __nv_bfloat162 t = __floats2bfloat162_rn(a, b);
    return *(uint32_t*)&t;
}

// ---------------- bt sum ----------------
__global__ void btsum_k(const float* __restrict__ bt) {
    int e = blockIdx.x * blockDim.x + threadIdx.x;
    if (e < Dd) {
        float s = 0.f;
        #pragma unroll
        for (int u = 0; u < Tt; u++) s += bt[u * Dd + e];
        g_btsum[e] = s;
    }
}

// ---------------- weight fp32 -> bf16 hi/lo ----------------
__global__ void wcvt_k(const float* __restrict__ src, __nv_bfloat16* __restrict__ hi,
                       __nv_bfloat16* __restrict__ lo, int n) {
    int i = blockIdx.x * blockDim.x + threadIdx.x;
    if (i < n) {
        float v = src[i];
        __nv_bfloat16 h = __float2bfloat16(v);
        hi[i] = h;
        lo[i] = __float2bfloat16(v - __bfloat162float(h));
    }
}

// ---------------- LayerNorm -> bf16 hi/lo (optional +pos) ----------------
__global__ void ln_bf_k(const float* __restrict__ in,
                        const float* __restrict__ al,
                        const float* __restrict__ be,
                        const float* __restrict__ pos,
                        __nv_bfloat16* __restrict__ oh,
                        __nv_bfloat16* __restrict__ ol,
                        int posmod) {
    int row = blockIdx.x;
    int tid = threadIdx.x;
    const float2* rin = (const float2*)(in + (size_t)row * Dd);
    float2 v = rin[tid];
    float s  = v.x + v.y;
    float sq = v.x * v.x + v.y * v.y;
    #pragma unroll
    for (int o = 16; o; o >>= 1) {
        s  += __shfl_xor_sync(0xffffffffu, s,  o);
        sq += __shfl_xor_sync(0xffffffffu, sq, o);
    }
    __shared__ float ss[8], ssq[8];
    int w = tid >> 5;
    if ((tid & 31) == 0) { ss[w] = s; ssq[w] = sq; }
    __syncthreads();
    s = 0.f; sq = 0.f;
    #pragma unroll
    for (int i = 0; i < 8; i++) { s += ss[i]; sq += ssq[i]; }
    float mu  = s * (1.0f / Dd);
    float var = (sq - (float)Dd * mu * mu) * (1.0f / (Dd - 1));
    float inv = 1.0f / (sqrtf(fmaxf(var, 0.f)) + EPSV);

    float2 a = ((const float2*)al)[tid];
    float2 b = ((const float2*)be)[tid];
    float ox = a.x * (v.x - mu) * inv + b.x;
    float oy = a.y * (v.y - mu) * inv + b.y;
    if (pos) {
        const float2* pr = (const float2*)(pos + (size_t)(row % posmod) * Dd);
        float2 p = pr[tid];
        ox += p.x; oy += p.y;
    }
    __nv_bfloat16 hx = __float2bfloat16(ox);
    __nv_bfloat16 hy = __float2bfloat16(oy);
    __nv_bfloat16 lx = __float2bfloat16(ox - __bfloat162float(hx));
    __nv_bfloat16 ly = __float2bfloat16(oy - __bfloat162float(hy));
    ((__nv_bfloat162*)(oh + (size_t)row * Dd))[tid] = __nv_bfloat162(hx, hy);
    ((__nv_bfloat162*)(ol + (size_t)row * Dd))[tid] = __nv_bfloat162(lx, ly);
}

// ================= mma.sync bf16x3 GEMM ======================
// modes: 0: Cf = acc + bias
//        1 (tc): Cf = res + gelu(acc/12 + bias); A is [b,t,u,p,d], B per-u
//        2: Chi/Clo = split(gelu(acc + bias))
//        3: Cf = res + gelu(acc + bias)
//        4: Chi/Clo = split(acc + bias)
#define LDSE 72
#define TILE_B (128*LDSE*2)
#define STAGE_B (4*TILE_B)
#define GM_SMEM (2*STAGE_B)

__global__ void __launch_bounds__(256, 1) gemm_mma_k(
    const __nv_bfloat16* __restrict__ Ahi, const __nv_bfloat16* __restrict__ Alo,
    const __nv_bfloat16* __restrict__ Bhi, const __nv_bfloat16* __restrict__ Blo,
    const float* __restrict__ bias, const float* __restrict__ res,
    float* __restrict__ Cf, __nv_bfloat16* __restrict__ Chi, __nv_bfloat16* __restrict__ Clo,
    int M, int N, int K, int mode)
{
    extern __shared__ char smc[];
    int tid = threadIdx.x;
    int wid = tid >> 5, lane = tid & 31;
    int bm = blockIdx.y * 128, bn = blockIdx.x * 128;
    int wm = (wid >> 2) * 64;
    int wn = (wid & 3) * 32;

    int lrow = tid >> 1;
    int lhalf = tid & 1;
    int am = min(bm + lrow, M - 1);
    size_t abase;
    if (mode == 1) {
        int b_ = am / (Tt * Pp), r_ = am % (Tt * Pp);
        int t_ = r_ / Pp, p_ = r_ % Pp;
        abase = ((size_t)(b_ * (Tt * Tt) + t_ * Tt) * Pp + p_) * Dd;
    } else {
        abase = (size_t)am * K;
    }
    int brow = bn + lrow;
    uint32_t smrow = lrow * (LDSE * 2);

    int NC = K / 64;

    auto load_stage = [&](int buf, int c) {
        size_t aoff, boff;
        if (mode == 1) {
            int u = c >> 3, d0 = (c & 7) * 64;
            aoff = abase + (size_t)u * (Pp * Dd) + d0;
            boff = (size_t)u * (Dd * Dd) + (size_t)brow * Dd + d0;
        } else {
            aoff = abase + c * 64;
            boff = (size_t)brow * K + c * 64;
        }
        uint32_t sb = smem_u32(smc) + buf * STAGE_B + smrow;
        #pragma unroll
        for (int i = 0; i < 4; i++) {
            int colk = lhalf * 32 + i * 8;
            uint32_t so = sb + colk * 2;
            cpa16(so,              Ahi + aoff + colk);
            cpa16(so + TILE_B,     Alo + aoff + colk);
            cpa16(so + 2*TILE_B,   Bhi + boff + colk);
            cpa16(so + 3*TILE_B,   Blo + boff + colk);
        }
    };

    int sel = lane >> 3, lr = lane & 7;
    int a_m = wm + (sel & 1) * 8 + lr;
    int a_k = (sel >> 1) * 8;
    int b_n = wn + (sel >> 1) * 8 + lr;
    int b_k = (sel & 1) * 8;
    uint32_t smb = smem_u32(smc);
    uint32_t aoffB = (a_m * LDSE + a_k) * 2;
    uint32_t boffB = (b_n * LDSE + b_k) * 2;

    float acc[4][4][4] = {};

    load_stage(0, 0);
    CPA_COMMIT();

    for (int c = 0; c < NC; c++) {
        int buf = c & 1;
        if (c + 1 < NC) {
            load_stage(buf ^ 1, c + 1);
            CPA_COMMIT();
            CPA_WAIT(1);
        } else {
            CPA_WAIT(0);
        }
        __syncthreads();

        uint32_t base = smb + buf * STAGE_B;
        uint32_t aHb = base + aoffB;
        uint32_t aLb = aHb + TILE_B;
        uint32_t bHb = base + 2*TILE_B + boffB;
        uint32_t bLb = bHb + TILE_B;

        #pragma unroll
        for (int kk = 0; kk < 4; kk++) {
            uint32_t ko = kk * 32;
            uint32_t aH[4][4], aL[4][4], bH[2][4], bL[2][4];
            #pragma unroll
            for (int mt = 0; mt < 4; mt++) {
                ldsm4(aH[mt], aHb + mt * (16 * LDSE * 2) + ko);
                ldsm4(aL[mt], aLb + mt * (16 * LDSE * 2) + ko);
            }
            #pragma unroll
            for (int nt2 = 0; nt2 < 2; nt2++) {
                ldsm4(bH[nt2], bHb + nt2 * (16 * LDSE * 2) + ko);
                ldsm4(bL[nt2], bLb + nt2 * (16 * LDSE * 2) + ko);
            }
            #pragma unroll
            for (int mt = 0; mt < 4; mt++) {
                #pragma unroll
                for (int nt = 0; nt < 4; nt++) {
                    int s2 = nt >> 1, pp = (nt & 1) * 2;
                    mma_bf16(acc[mt][nt], aH[mt], bH[s2][pp], bH[s2][pp+1]);
                    mma_bf16(acc[mt][nt], aH[mt], bL[s2][pp], bL[s2][pp+1]);
                    mma_bf16(acc[mt][nt], aL[mt], bH[s2][pp], bH[s2][pp+1]);
                }
            }
        }
        __syncthreads();
    }

    int qrow = lane >> 2;
    int qcol = (lane & 3) * 2;
    #pragma unroll
    for (int mt = 0; mt < 4; mt++) {
        #pragma unroll
        for (int nt = 0; nt < 4; nt++) {
            float* cc = acc[mt][nt];
            int n0 = bn + wn + nt * 8 + qcol;
            float b0 = bias[n0], b1 = bias[n0 + 1];
            #pragma unroll
            for (int hrow = 0; hrow < 2; hrow++) {
                int m = bm + wm + mt * 16 + qrow + hrow * 8;
                if (m >= M) continue;
                float a0 = cc[hrow * 2 + 0];
                float a1 = cc[hrow * 2 + 1];
                size_t off = (size_t)m * N + n0;
                float v0, v1;
                if (mode == 0) {
                    v0 = a0 + b0; v1 = a1 + b1;
                } else if (mode == 1) {
                    float2 r = *(const float2*)&res[off];
                    v0 = r.x + gelu_exact(a0 * (1.0f / Tt) + b0);
                    v1 = r.y + gelu_exact(a1 * (1.0f / Tt) + b1);
                } else if (mode == 3) {
                    float2 r = *(const float2*)&res[off];
                    v0 = r.x + gelu_exact(a0 + b0);
                    v1 = r.y + gelu_exact(a1 + b1);
                } else { // mode 2 or 4
                    float g0 = (mode == 2) ? gelu_exact(a0 + b0) : (a0 + b0);
                    float g1 = (mode == 2) ? gelu_exact(a1 + b1) : (a1 + b1);
                    __nv_bfloat16 h0 = __float2bfloat16(g0);
                    __nv_bfloat16 h1 = __float2bfloat16(g1);
                    __nv_bfloat16 l0 = __float2bfloat16(g0 - __bfloat162float(h0));
                    __nv_bfloat16 l1 = __float2bfloat16(g1 - __bfloat162float(h1));
                    *(__nv_bfloat162*)(Chi + off) = __nv_bfloat162(h0, h1);
                    *(__nv_bfloat162*)(Clo + off) = __nv_bfloat162(l0, l1);
                    continue;
                }
                *(float2*)&Cf[off] = make_float2(v0, v1);
            }
        }
    }
}

// ================= tensor-core attention (bf16x3) ======================
// one block per (b,t,u,h); 7 warps; M-tiles of 16 queries (13 tiles).
// K smem [208][72] hi/lo; V^T smem [64][224] hi/lo; Q frags from gmem;
// P fragments built in-register from S accumulator (identical lane mapping).
#define AKR 208
#define AKP 72
#define AVP 224
#define ASM_K (AKR*AKP*2)     // 29952 bytes
#define ASM_V (64*AVP*2)      // 28672 bytes
#define ATT_SMEM (2*ASM_K + 2*ASM_V)   // 117248

__global__ void __launch_bounds__(224, 1) attn_mma_k() {
    int bid = blockIdx.x;
    int h = bid & 7;
    int u = (bid >> 3) % Tt;
    int t = (bid / (Hh * Tt)) % Tt;
    int b = bid / (Hh * Tt * Tt);

    extern __shared__ char smb_[];
    uint32_t skh = smem_u32(smb_);
    uint32_t skl = skh + ASM_K;
    uint32_t svh = skh + 2 * ASM_K;
    uint32_t svl = svh + ASM_V;

    int tid = threadIdx.x;
    int w = tid >> 5, lane = tid & 31;

    size_t kvbase = ((size_t)(b * Tt + u) * Pp) * Dd + h * DHd;
    size_t qbase  = ((size_t)(b * Tt + t) * Pp) * Dd + h * DHd;
    float* Ob = g_av + ((size_t)((b * Tt + t) * Tt + u) * Pp) * Dd + h * DHd;

    // ---- load K hi/lo into [208][72] smem (row = 144B)
    for (int idx = tid; idx < AKR * 8; idx += 224) {
        int row = idx >> 3, seg = idx & 7;
        uint4 vh4 = make_uint4(0, 0, 0, 0), vl4 = vh4;
        if (row < Pp) {
            vh4 = *(const uint4*)&g_kh[kvbase + (size_t)row * Dd + seg * 8];
            vl4 = *(const uint4*)&g_kl[kvbase + (size_t)row * Dd + seg * 8];
        }
        *(uint4*)(smb_ + row * 144 + seg * 16) = vh4;
        *(uint4*)(smb_ + ASM_K + row * 144 + seg * 16) = vl4;
    }
    // ---- load V^T hi/lo into [64][224] smem (transposed)
    {
        const uint16_t* Vh16 = (const uint16_t*)g_vh;
        const uint16_t* Vl16 = (const uint16_t*)g_vl;
        uint16_t* sVh16 = (uint16_t*)(smb_ + 2 * ASM_K);
        uint16_t* sVl16 = (uint16_t*)(smb_ + 2 * ASM_K + ASM_V);
        for (int idx = tid; idx < AKR * 64; idx += 224) {
            int key = idx >> 6, dh = idx & 63;
            uint16_t vv = 0, vl = 0;
            if (key < Pp) {
                vv = Vh16[kvbase + (size_t)key * Dd + dh];
                vl = Vl16[kvbase + (size_t)key * Dd + dh];
            }
            sVh16[dh * AVP + key] = vv;
            sVl16[dh * AVP + key] = vl;
        }
    }
    __syncthreads();

    int gr = lane >> 2, qc = (lane & 3) * 2;
    int sel = lane >> 3, lr = lane & 7;
    uint32_t koff = (((sel >> 1) * 8 + lr)) * 144 + (sel & 1) * 16;
    uint32_t voff = (((sel >> 1) * 8 + lr)) * 448 + (sel & 1) * 16;

    for (int mt = w; mt < 13; mt += 7) {
        int m0 = mt * 16;
        int r0 = min(m0 + gr, Pp - 1);
        int r1 = min(m0 + gr + 8, Pp - 1);

        // ---- Q fragments from gmem
        uint32_t qa_h[4][4], qa_l[4][4];
        #pragma unroll
        for (int J = 0; J < 4; J++) {
            int c0 = J * 16 + qc;
            qa_h[J][0] = *(const uint32_t*)&g_qh[qbase + (size_t)r0 * Dd + c0];
            qa_h[J][1] = *(const uint32_t*)&g_qh[qbase + (size_t)r1 * Dd + c0];
            qa_h[J][2] = *(const uint32_t*)&g_qh[qbase + (size_t)r0 * Dd + c0 + 8];
            qa_h[J][3] = *(const uint32_t*)&g_qh[qbase + (size_t)r1 * Dd + c0 + 8];
            qa_l[J][0] = *(const uint32_t*)&g_ql[qbase + (size_t)r0 * Dd + c0];
            qa_l[J][1] = *(const uint32_t*)&g_ql[qbase + (size_t)r1 * Dd + c0];
            qa_l[J][2] = *(const uint32_t*)&g_ql[qbase + (size_t)r0 * Dd + c0 + 8];
            qa_l[J][3] = *(const uint32_t*)&g_ql[qbase + (size_t)r1 * Dd + c0 + 8];
        }

        // ---- S = Q K^T  : acc sc[26][4]
        float sc[26][4];
        #pragma unroll
        for (int nt = 0; nt < 26; nt++)
            #pragma unroll
            for (int i = 0; i < 4; i++) sc[nt][i] = 0.f;

        for (int ntp = 0; ntp < 13; ntp++) {
            uint32_t kb = ntp * (16 * 144) + koff;
            #pragma unroll
            for (int J = 0; J < 4; J++) {
                uint32_t bh[4], bl[4];
                ldsm4(bh, skh + kb + J * 32);
                ldsm4(bl, skl + kb + J * 32);
                mma_bf16(sc[2*ntp],   qa_h[J], bh[0], bh[1]);
                mma_bf16(sc[2*ntp],   qa_h[J], bl[0], bl[1]);
                mma_bf16(sc[2*ntp],   qa_l[J], bh[0], bh[1]);
                mma_bf16(sc[2*ntp+1], qa_h[J], bh[2], bh[3]);
                mma_bf16(sc[2*ntp+1], qa_h[J], bl[2], bl[3]);
                mma_bf16(sc[2*ntp+1], qa_l[J], bh[2], bh[3]);
            }
        }

        // ---- softmax (registers, 4-lane row groups)
        float mx0 = -1e30f, mx1 = -1e30f;
        #pragma unroll
        for (int nt = 0; nt < 26; nt++) {
            int n0 = nt * 8 + qc;
            if (n0 >= Pp) {
                sc[nt][0] = sc[nt][1] = sc[nt][2] = sc[nt][3] = -1e30f;
            } else {
                sc[nt][0] *= 0.125f; sc[nt][1] *= 0.125f;
                sc[nt][2] *= 0.125f; sc[nt][3] *= 0.125f;
            }
            mx0 = fmaxf(mx0, fmaxf(sc[nt][0], sc[nt][1]));
            mx1 = fmaxf(mx1, fmaxf(sc[nt][2], sc[nt][3]));
        }
        mx0 = fmaxf(mx0, __shfl_xor_sync(0xffffffffu, mx0, 1));
        mx0 = fmaxf(mx0, __shfl_xor_sync(0xffffffffu, mx0, 2));
        mx1 = fmaxf(mx1, __shfl_xor_sync(0xffffffffu, mx1, 1));
        mx1 = fmaxf(mx1, __shfl_xor_sync(0xffffffffu, mx1, 2));
        float sum0 = 0.f, sum1 = 0.f;
        #pragma unroll
        for (int nt = 0; nt < 26; nt++) {
            sc[nt][0] = __expf(sc[nt][0] - mx0);
            sc[nt][1] = __expf(sc[nt][1] - mx0);
            sc[nt][2] = __expf(sc[nt][2] - mx1);
            sc[nt][3] = __expf(sc[nt][3] - mx1);
            sum0 += sc[nt][0] + sc[nt][1];
            sum1 += sc[nt][2] + sc[nt][3];
        }
        sum0 += __shfl_xor_sync(0xffffffffu, sum0, 1);
        sum0 += __shfl_xor_sync(0xffffffffu, sum0, 2);
        sum1 += __shfl_xor_sync(0xffffffffu, sum1, 1);
        sum1 += __shfl_xor_sync(0xffffffffu, sum1, 2);
        float rv0 = 1.0f / sum0, rv1 = 1.0f / sum1;
        #pragma unroll
        for (int nt = 0; nt < 26; nt++) {
            sc[nt][0] *= rv0; sc[nt][1] *= rv0;
            sc[nt][2] *= rv1; sc[nt][3] *= rv1;
        }

        // ---- O = P V : oacc[8][4]
        float oacc[8][4];
        #pragma unroll
        for (int i = 0; i < 8; i++)
            #pragma unroll
            for (int jx = 0; jx < 4; jx++) oacc[i][jx] = 0.f;

        for (int J = 0; J < 13; J++) {
            // P A-fragment from S registers: same-lane remap
            uint32_t pa_h[4], pa_l[4];
            {
                float p00 = sc[2*J][0],   p01 = sc[2*J][1];
                float p10 = sc[2*J][2],   p11 = sc[2*J][3];
                float p20 = sc[2*J+1][0], p21 = sc[2*J+1][1];
                float p30 = sc[2*J+1][2], p31 = sc[2*J+1][3];
                __nv_bfloat16 h;
                float l00, l01, l10, l11, l20, l21, l30, l31;
                h = __float2bfloat16(p00); l00 = p00 - __bfloat162float(h);
                h = __float2bfloat16(p01); l01 = p01 - __bfloat162float(h);
                h = __float2bfloat16(p10); l10 = p10 - __bfloat162float(h);
                h = __float2bfloat16(p11); l11 = p11 - __bfloat162float(h);
                h = __float2bfloat16(p20); l20 = p20 - __bfloat162float(h);
                h = __float2bfloat16(p21); l21 = p21 - __bfloat162float(h);
                h = __float2bfloat16(p30); l30 = p30 - __bfloat162float(h);
                h = __float2bfloat16(p31); l31 = p31 - __bfloat162float(h);
                pa_h[0] = pack_bf16(p00, p01);
                pa_h[1] = pack_bf16(p10, p11);
                pa_h[2] = pack_bf16(p20, p21);
                pa_h[3] = pack_bf16(p30, p31);
                pa_l[0] = pack_bf16(l00, l01);
                pa_l[1] = pack_bf16(l10, l11);
                pa_l[2] = pack_bf16(l20, l21);
                pa_l[3] = pack_bf16(l30, l31);
            }
            uint32_t vb = voff + J * 32;
            #pragma unroll
            for (int np = 0; np < 4; np++) {
                uint32_t bh[4], bl[4];
                ldsm4(bh, svh + np * (16 * 448) + vb);
                ldsm4(bl, svl + np * (16 * 448) + vb);
                mma_bf16(oacc[2*np],   pa_h, bh[0], bh[1]);
                mma_bf16(oacc[2*np],   pa_h, bl[0], bl[1]);
                mma_bf16(oacc[2*np],   pa_l, bh[0], bh[1]);
                mma_bf16(oacc[2*np+1], pa_h, bh[2], bh[3]);
                mma_bf16(oacc[2*np+1], pa_h, bl[2], bl[3]);
                mma_bf16(oacc[2*np+1], pa_l, bh[2], bh[3]);
            }
        }

        // ---- store O
        int p0r = m0 + gr, p1r = m0 + gr + 8;
        #pragma unroll
        for (int nt2 = 0; nt2 < 8; nt2++) {
            int n = nt2 * 8 + qc;
            if (p0r < Pp)
                *(float2*)&Ob[(size_t)p0r * Dd + n] = make_float2(oacc[nt2][0], oacc[nt2][1]);
            if (p1r < Pp)
                *(float2*)&Ob[(size_t)p1r * Dd + n] = make_float2(oacc[nt2][2], oacc[nt2][3]);
        }
    }
}

// ---------------- launch ----------------
extern "C" void kernel_launch(void* const* d_in, const int* in_sizes, int n_in,
                              void* d_out, int out_size) {
    const float* x    = (const float*)d_in[0];
    const float* Wq   = (const float*)d_in[1];
    const float* bq   = (const float*)d_in[2];
    const float* Wk   = (const float*)d_in[3];
    const float* bk   = (const float*)d_in[4];
    const float* Wv   = (const float*)d_in[5];
    const float* bv   = (const float*)d_in[6];
    const float* in_a = (const float*)d_in[7];
    const float* in_b = (const float*)d_in[8];
    const float* at_a = (const float*)d_in[9];
    const float* at_b = (const float*)d_in[10];
    const float* ou_a = (const float*)d_in[11];
    const float* ou_b = (const float*)d_in[12];
    const float* Wt   = (const float*)d_in[13];
    const float* bt   = (const float*)d_in[14];
    const float* pos  = (const float*)d_in[15];
    const float* W1   = (const float*)d_in[16];
    const float* b1   = (const float*)d_in[17];
    const float* W2   = (const float*)d_in[18];
    const float* b2   = (const float*)d_in[19];

    float *pav, *pxres, *pbtsum;
    __nv_bfloat16 *px2h, *px2l, *pyh, *pyl, *phh, *phl, *pwh, *pwl;
    __nv_bfloat16 *pqh, *pql, *pkh, *pkl, *pvh, *pvl;
    cudaGetSymbolAddress((void**)&pav,  g_av);
    cudaGetSymbolAddress((void**)&pxres,g_xres);
    cudaGetSymbolAddress((void**)&pbtsum, g_btsum);
    cudaGetSymbolAddress((void**)&px2h, g_x2h);
    cudaGetSymbolAddress((void**)&px2l, g_x2l);
    cudaGetSymbolAddress((void**)&pyh,  g_yh);
    cudaGetSymbolAddress((void**)&pyl,  g_yl);
    cudaGetSymbolAddress((void**)&phh,  g_hh);
    cudaGetSymbolAddress((void**)&phl,  g_hl);
    cudaGetSymbolAddress((void**)&pwh,  w_hi);
    cudaGetSymbolAddress((void**)&pwl,  w_lo);
    cudaGetSymbolAddress((void**)&pqh,  g_qh);
    cudaGetSymbolAddress((void**)&pql,  g_ql);
    cudaGetSymbolAddress((void**)&pkh,  g_kh);
    cudaGetSymbolAddress((void**)&pkl,  g_kl);
    cudaGetSymbolAddress((void**)&pvh,  g_vh);
    cudaGetSymbolAddress((void**)&pvl,  g_vl);

    cudaFuncSetAttribute(attn_mma_k, cudaFuncAttributeMaxDynamicSharedMemorySize,
                         ATT_SMEM);
    cudaFuncSetAttribute(gemm_mma_k, cudaFuncAttributeMaxDynamicSharedMemorySize,
                         GM_SMEM);

    // weight conversions
    wcvt_k<<<(262144 + 255) / 256, 256>>>(Wq, pwh + OQ,  pwl + OQ,  262144);
    wcvt_k<<<(262144 + 255) / 256, 256>>>(Wk, pwh + OKo, pwl + OKo, 262144);
    wcvt_k<<<(262144 + 255) / 256, 256>>>(Wv, pwh + OV,  pwl + OV,  262144);
    wcvt_k<<<(3145728 + 255) / 256, 256>>>(Wt, pwh + OT, pwl + OT, 3145728);
    wcvt_k<<<(524288 + 255) / 256, 256>>>(W1, pwh + O1,  pwl + O1,  524288);
    wcvt_k<<<(524288 + 255) / 256, 256>>>(W2, pwh + O2,  pwl + O2,  524288);
    btsum_k<<<2, 256>>>(bt);

    // LN(x) -> x2 hi/lo
    ln_bf_k<<<M1, 256>>>(x, in_a, in_b, nullptr, px2h, px2l, 1);

    // QKV projections (mode 4: bf16 hi/lo out)
    dim3 gqkv(Dd / 128, (M1 + 127) / 128);
    gemm_mma_k<<<gqkv, 256, GM_SMEM>>>(px2h, px2l, pwh + OQ,  pwl + OQ,  bq, nullptr, nullptr, pqh, pql, M1, Dd, Dd, 4);
    gemm_mma_k<<<gqkv, 256, GM_SMEM>>>(px2h, px2l, pwh + OKo, pwl + OKo, bk, nullptr, nullptr, pkh, pkl, M1, Dd, Dd, 4);
    gemm_mma_k<<<gqkv, 256, GM_SMEM>>>(px2h, px2l, pwh + OV,  pwl + OV,  bv, nullptr, nullptr, pvh, pvl, M1, Dd, Dd, 4);

    // tensor-core attention -> g_av (fp32)
    attn_mma_k<<<Bq * Tt * Tt * Hh, 224, ATT_SMEM>>>();

    // LN(av)+pos -> y hi/lo
    ln_bf_k<<<ROWS_AV, 256>>>(pav, at_a, at_b, pos, pyh, pyl, POSMOD);

    // tc contraction (mode 1)
    gemm_mma_k<<<gqkv, 256, GM_SMEM>>>(pyh, pyl, pwh + OT, pwl + OT, pbtsum, x, pxres, nullptr, nullptr, M1, Dd, Tt * Dd, 1);

    // LN(xres) -> x2 hi/lo
    ln_bf_k<<<M1, 256>>>(pxres, ou_a, ou_b, nullptr, px2h, px2l, 1);

    // MLP1 (mode 2) -> h hi/lo
    dim3 g1(2 * Dd / 128, (M1 + 127) / 128);
    gemm_mma_k<<<g1, 256, GM_SMEM>>>(px2h, px2l, pwh + O1, pwl + O1, b1, nullptr, nullptr, phh, phl, M1, 2 * Dd, Dd, 2);

    // MLP2 (mode 3) -> d_out
    gemm_mma_k<<<gqkv, 256, GM_SMEM>>>(phh, phl, pwh + O2, pwl + O2, b2, pxres, (float*)d_out, nullptr, nullptr, M1, Dd, 2 * Dd, 3);
}

// round 6
// speedup vs baseline: 3.9851x; 1.1846x over previous
#include <cuda_runtime.h>
#include <cuda_bf16.h>
#include <math.h>
#include <stdint.h>

#define Bq 4
#define Tt 12
#define Pp 196
#define Dd 512
#define Hh 8
#define DHd 64
#define EPSV 1e-6f

#define M1 (Bq*Tt*Pp)            // 9408
#define ROWS_AV (Bq*Tt*Tt*Pp)    // 112896
#define POSMOD (Tt*Tt*Pp)        // 28224

// weight offsets in converted buffer
#define OQ 0
#define OKo 262144
#define OV  524288
#define OT  786432
#define O1  3932160
#define O2  4456448
#define WTOT 4980736

// ---------------- scratch ----------------
__device__ float g_av[(size_t)ROWS_AV*Dd];
__device__ float g_xres[M1*Dd];
__device__ float g_btsum[Dd];
__device__ __nv_bfloat16 g_x2h[M1*Dd],  g_x2l[M1*Dd];
__device__ __nv_bfloat16 g_qh[M1*Dd], g_ql[M1*Dd];
__device__ __nv_bfloat16 g_kh[M1*Dd], g_kl[M1*Dd];
__device__ __nv_bfloat16 g_vh[M1*Dd], g_vl[M1*Dd];
__device__ __nv_bfloat16 g_yh[(size_t)ROWS_AV*Dd], g_yl[(size_t)ROWS_AV*Dd];
__device__ __nv_bfloat16 g_hh[M1*2*Dd], g_hl[M1*2*Dd];
__device__ __nv_bfloat16 w_hi[WTOT], w_lo[WTOT];

// ---------------- helpers ----------------
__device__ __forceinline__ float gelu_exact(float x) {
    return 0.5f * x * (1.0f + erff(x * 0.70710678118654752f));
}
__device__ __forceinline__ uint32_t smem_u32(const void* p) {
    uint32_t a;
    asm("{ .reg .u64 t; cvta.to.shared.u64 t, %1; cvt.u32.u64 %0, t; }" : "=r"(a) : "l"(p));
    return a;
}
__device__ __forceinline__ void ldsm4(uint32_t* r, uint32_t a) {
    asm volatile("ldmatrix.sync.aligned.m8n8.x4.shared.b16 {%0,%1,%2,%3}, [%4];"
                 : "=r"(r[0]), "=r"(r[1]), "=r"(r[2]), "=r"(r[3]) : "r"(a));
}
__device__ __forceinline__ void ldsm4t(uint32_t* r, uint32_t a) {
    asm volatile("ldmatrix.sync.aligned.m8n8.x4.trans.shared.b16 {%0,%1,%2,%3}, [%4];"
                 : "=r"(r[0]), "=r"(r[1]), "=r"(r[2]), "=r"(r[3]) : "r"(a));
}
__device__ __forceinline__ void mma_bf16(float* c, const uint32_t* a, uint32_t b0, uint32_t b1) {
    asm volatile(
        "mma.sync.aligned.m16n8k16.row.col.f32.bf16.bf16.f32 "
        "{%0,%1,%2,%3}, {%4,%5,%6,%7}, {%8,%9}, {%0,%1,%2,%3};"
        : "+f"(c[0]), "+f"(c[1]), "+f"(c[2]), "+f"(c[3])
        : "r"(a[0]), "r"(a[1]), "r"(a[2]), "r"(a[3]), "r"(b0), "r"(b1));
}
__device__ __forceinline__ void cpa16(uint32_t s, const void* g) {
    asm volatile("cp.async.cg.shared.global [%0], [%1], 16;" :: "r"(s), "l"(g));
}
#define CPA_COMMIT() asm volatile("cp.async.commit_group;" ::: "memory")
#define CPA_WAIT(n)  asm volatile("cp.async.wait_group %0;" :: "n"(n) : "memory")

__device__ __forceinline__ uint32_t pack_bf16(float a, float b) {
    __nv_bfloat162 t = __floats2bfloat162_rn(a, b);
    return *(uint32_t*)&t;
}

// ---------------- bt sum ----------------
__global__ void btsum_k(const float* __restrict__ bt) {
    int e = blockIdx.x * blockDim.x + threadIdx.x;
    if (e < Dd) {
        float s = 0.f;
        #pragma unroll
        for (int u = 0; u < Tt; u++) s += bt[u * Dd + e];
        g_btsum[e] = s;
    }
}

// ---------------- weight fp32 -> bf16 hi/lo ----------------
__global__ void wcvt_k(const float* __restrict__ src, __nv_bfloat16* __restrict__ hi,
                       __nv_bfloat16* __restrict__ lo, int n) {
    int i = blockIdx.x * blockDim.x + threadIdx.x;
    if (i < n) {
        float v = src[i];
        __nv_bfloat16 h = __float2bfloat16(v);
        hi[i] = h;
        lo[i] = __float2bfloat16(v - __bfloat162float(h));
    }
}

// ---------------- LayerNorm -> bf16 hi/lo (optional +pos) ----------------
__global__ void ln_bf_k(const float* __restrict__ in,
                        const float* __restrict__ al,
                        const float* __restrict__ be,
                        const float* __restrict__ pos,
                        __nv_bfloat16* __restrict__ oh,
                        __nv_bfloat16* __restrict__ ol,
                        int posmod) {
    int row = blockIdx.x;
    int tid = threadIdx.x;
    const float2* rin = (const float2*)(in + (size_t)row * Dd);
    float2 v = rin[tid];
    float s  = v.x + v.y;
    float sq = v.x * v.x + v.y * v.y;
    #pragma unroll
    for (int o = 16; o; o >>= 1) {
        s  += __shfl_xor_sync(0xffffffffu, s,  o);
        sq += __shfl_xor_sync(0xffffffffu, sq, o);
    }
    __shared__ float ss[8], ssq[8];
    int w = tid >> 5;
    if ((tid & 31) == 0) { ss[w] = s; ssq[w] = sq; }
    __syncthreads();
    s = 0.f; sq = 0.f;
    #pragma unroll
    for (int i = 0; i < 8; i++) { s += ss[i]; sq += ssq[i]; }
    float mu  = s * (1.0f / Dd);
    float var = (sq - (float)Dd * mu * mu) * (1.0f / (Dd - 1));
    float inv = 1.0f / (sqrtf(fmaxf(var, 0.f)) + EPSV);

    float2 a = ((const float2*)al)[tid];
    float2 b = ((const float2*)be)[tid];
    float ox = a.x * (v.x - mu) * inv + b.x;
    float oy = a.y * (v.y - mu) * inv + b.y;
    if (pos) {
        const float2* pr = (const float2*)(pos + (size_t)(row % posmod) * Dd);
        float2 p = pr[tid];
        ox += p.x; oy += p.y;
    }
    __nv_bfloat16 hx = __float2bfloat16(ox);
    __nv_bfloat16 hy = __float2bfloat16(oy);
    __nv_bfloat16 lx = __float2bfloat16(ox - __bfloat162float(hx));
    __nv_bfloat16 ly = __float2bfloat16(oy - __bfloat162float(hy));
    ((__nv_bfloat162*)(oh + (size_t)row * Dd))[tid] = __nv_bfloat162(hx, hy);
    ((__nv_bfloat162*)(ol + (size_t)row * Dd))[tid] = __nv_bfloat162(lx, ly);
}

// ================= mma.sync bf16x3 GEMM ======================
// modes: 0: Cf = acc + bias
//        1 (tc): Cf = res + gelu(acc/12 + bias); A is [b,t,u,p,d], B per-u
//        2: Chi/Clo = split(gelu(acc + bias))
//        3: Cf = res + gelu(acc + bias)
//        4: Chi/Clo = split(acc + bias)
#define LDSE 72
#define TILE_B (128*LDSE*2)
#define STAGE_B (4*TILE_B)
#define GM_SMEM (2*STAGE_B)

__global__ void __launch_bounds__(256, 1) gemm_mma_k(
    const __nv_bfloat16* __restrict__ Ahi, const __nv_bfloat16* __restrict__ Alo,
    const __nv_bfloat16* __restrict__ Bhi, const __nv_bfloat16* __restrict__ Blo,
    const float* __restrict__ bias, const float* __restrict__ res,
    float* __restrict__ Cf, __nv_bfloat16* __restrict__ Chi, __nv_bfloat16* __restrict__ Clo,
    int M, int N, int K, int mode)
{
    extern __shared__ char smc[];
    int tid = threadIdx.x;
    int wid = tid >> 5, lane = tid & 31;
    int bm = blockIdx.y * 128, bn = blockIdx.x * 128;
    int wm = (wid >> 2) * 64;
    int wn = (wid & 3) * 32;

    int lrow = tid >> 1;
    int lhalf = tid & 1;
    int am = min(bm + lrow, M - 1);
    size_t abase;
    if (mode == 1) {
        int b_ = am / (Tt * Pp), r_ = am % (Tt * Pp);
        int t_ = r_ / Pp, p_ = r_ % Pp;
        abase = ((size_t)(b_ * (Tt * Tt) + t_ * Tt) * Pp + p_) * Dd;
    } else {
        abase = (size_t)am * K;
    }
    int brow = bn + lrow;
    uint32_t smrow = lrow * (LDSE * 2);

    int NC = K / 64;

    auto load_stage = [&](int buf, int c) {
        size_t aoff, boff;
        if (mode == 1) {
            int u = c >> 3, d0 = (c & 7) * 64;
            aoff = abase + (size_t)u * (Pp * Dd) + d0;
            boff = (size_t)u * (Dd * Dd) + (size_t)brow * Dd + d0;
        } else {
            aoff = abase + c * 64;
            boff = (size_t)brow * K + c * 64;
        }
        uint32_t sb = smem_u32(smc) + buf * STAGE_B + smrow;
        #pragma unroll
        for (int i = 0; i < 4; i++) {
            int colk = lhalf * 32 + i * 8;
            uint32_t so = sb + colk * 2;
            cpa16(so,              Ahi + aoff + colk);
            cpa16(so + TILE_B,     Alo + aoff + colk);
            cpa16(so + 2*TILE_B,   Bhi + boff + colk);
            cpa16(so + 3*TILE_B,   Blo + boff + colk);
        }
    };

    int sel = lane >> 3, lr = lane & 7;
    int a_m = wm + (sel & 1) * 8 + lr;
    int a_k = (sel >> 1) * 8;
    int b_n = wn + (sel >> 1) * 8 + lr;
    int b_k = (sel & 1) * 8;
    uint32_t smb = smem_u32(smc);
    uint32_t aoffB = (a_m * LDSE + a_k) * 2;
    uint32_t boffB = (b_n * LDSE + b_k) * 2;

    float acc[4][4][4] = {};

    load_stage(0, 0);
    CPA_COMMIT();

    for (int c = 0; c < NC; c++) {
        int buf = c & 1;
        if (c + 1 < NC) {
            load_stage(buf ^ 1, c + 1);
            CPA_COMMIT();
            CPA_WAIT(1);
        } else {
            CPA_WAIT(0);
        }
        __syncthreads();

        uint32_t base = smb + buf * STAGE_B;
        uint32_t aHb = base + aoffB;
        uint32_t aLb = aHb + TILE_B;
        uint32_t bHb = base + 2*TILE_B + boffB;
        uint32_t bLb = bHb + TILE_B;

        #pragma unroll
        for (int kk = 0; kk < 4; kk++) {
            uint32_t ko = kk * 32;
            uint32_t aH[4][4], aL[4][4], bH[2][4], bL[2][4];
            #pragma unroll
            for (int mt = 0; mt < 4; mt++) {
                ldsm4(aH[mt], aHb + mt * (16 * LDSE * 2) + ko);
                ldsm4(aL[mt], aLb + mt * (16 * LDSE * 2) + ko);
            }
            #pragma unroll
            for (int nt2 = 0; nt2 < 2; nt2++) {
                ldsm4(bH[nt2], bHb + nt2 * (16 * LDSE * 2) + ko);
                ldsm4(bL[nt2], bLb + nt2 * (16 * LDSE * 2) + ko);
            }
            #pragma unroll
            for (int mt = 0; mt < 4; mt++) {
                #pragma unroll
                for (int nt = 0; nt < 4; nt++) {
                    int s2 = nt >> 1, pp = (nt & 1) * 2;
                    mma_bf16(acc[mt][nt], aH[mt], bH[s2][pp], bH[s2][pp+1]);
                    mma_bf16(acc[mt][nt], aH[mt], bL[s2][pp], bL[s2][pp+1]);
                    mma_bf16(acc[mt][nt], aL[mt], bH[s2][pp], bH[s2][pp+1]);
                }
            }
        }
        __syncthreads();
    }

    int qrow = lane >> 2;
    int qcol = (lane & 3) * 2;
    #pragma unroll
    for (int mt = 0; mt < 4; mt++) {
        #pragma unroll
        for (int nt = 0; nt < 4; nt++) {
            float* cc = acc[mt][nt];
            int n0 = bn + wn + nt * 8 + qcol;
            float b0 = bias[n0], b1 = bias[n0 + 1];
            #pragma unroll
            for (int hrow = 0; hrow < 2; hrow++) {
                int m = bm + wm + mt * 16 + qrow + hrow * 8;
                if (m >= M) continue;
                float a0 = cc[hrow * 2 + 0];
                float a1 = cc[hrow * 2 + 1];
                size_t off = (size_t)m * N + n0;
                float v0, v1;
                if (mode == 0) {
                    v0 = a0 + b0; v1 = a1 + b1;
                } else if (mode == 1) {
                    float2 r = *(const float2*)&res[off];
                    v0 = r.x + gelu_exact(a0 * (1.0f / Tt) + b0);
                    v1 = r.y + gelu_exact(a1 * (1.0f / Tt) + b1);
                } else if (mode == 3) {
                    float2 r = *(const float2*)&res[off];
                    v0 = r.x + gelu_exact(a0 + b0);
                    v1 = r.y + gelu_exact(a1 + b1);
                } else { // mode 2 or 4
                    float g0 = (mode == 2) ? gelu_exact(a0 + b0) : (a0 + b0);
                    float g1 = (mode == 2) ? gelu_exact(a1 + b1) : (a1 + b1);
                    __nv_bfloat16 h0 = __float2bfloat16(g0);
                    __nv_bfloat16 h1 = __float2bfloat16(g1);
                    __nv_bfloat16 l0 = __float2bfloat16(g0 - __bfloat162float(h0));
                    __nv_bfloat16 l1 = __float2bfloat16(g1 - __bfloat162float(h1));
                    *(__nv_bfloat162*)(Chi + off) = __nv_bfloat162(h0, h1);
                    *(__nv_bfloat162*)(Clo + off) = __nv_bfloat162(l0, l1);
                    continue;
                }
                *(float2*)&Cf[off] = make_float2(v0, v1);
            }
        }
    }
}

// ================= tensor-core attention (bf16x3) ======================
// one block per (b,t,u,h); 7 warps; M-tiles of 16 queries (13 tiles).
// K and V both row-major [208][72] bf16 hi/lo in smem (144B rows).
// QK^T uses non-trans ldmatrix on K; PV uses ldmatrix.trans on V.
// P fragments built in-register from S accumulator (identical lane mapping).
#define AKR 208
#define ALD 144
#define ASM_ONE (AKR*ALD)              // 29952 bytes
#define ATT_SMEM (4*ASM_ONE)           // 119808

__global__ void __launch_bounds__(224, 1) attn_mma_k() {
    int bid = blockIdx.x;
    int h = bid & 7;
    int u = (bid >> 3) % Tt;
    int t = (bid / (Hh * Tt)) % Tt;
    int b = bid / (Hh * Tt * Tt);

    extern __shared__ char smb_[];
    uint32_t skh = smem_u32(smb_);
    uint32_t skl = skh + ASM_ONE;
    uint32_t svh = skh + 2 * ASM_ONE;
    uint32_t svl = skh + 3 * ASM_ONE;

    int tid = threadIdx.x;
    int w = tid >> 5, lane = tid & 31;

    size_t kvbase = ((size_t)(b * Tt + u) * Pp) * Dd + h * DHd;
    size_t qbase  = ((size_t)(b * Tt + t) * Pp) * Dd + h * DHd;
    float* Ob = g_av + ((size_t)((b * Tt + t) * Tt + u) * Pp) * Dd + h * DHd;

    // ---- load K and V hi/lo into [208][72] smem (144B rows, zero-pad 196..207)
    for (int idx = tid; idx < AKR * 8; idx += 224) {
        int row = idx >> 3, seg = idx & 7;
        uint4 kh4 = make_uint4(0,0,0,0), kl4 = kh4, vh4 = kh4, vl4 = kh4;
        if (row < Pp) {
            size_t g = kvbase + (size_t)row * Dd + seg * 8;
            kh4 = *(const uint4*)&g_kh[g];
            kl4 = *(const uint4*)&g_kl[g];
            vh4 = *(const uint4*)&g_vh[g];
            vl4 = *(const uint4*)&g_vl[g];
        }
        uint32_t so = row * ALD + seg * 16;
        *(uint4*)(smb_ + so) = kh4;
        *(uint4*)(smb_ + ASM_ONE + so) = kl4;
        *(uint4*)(smb_ + 2*ASM_ONE + so) = vh4;
        *(uint4*)(smb_ + 3*ASM_ONE + so) = vl4;
    }
    __syncthreads();

    int gr = lane >> 2, qc = (lane & 3) * 2;
    int sel = lane >> 3, lr = lane & 7;
    // K (non-trans): row = n-half * 8 + lr, colbyte = k-half * 16
    uint32_t koff = ((sel >> 1) * 8 + lr) * ALD + (sel & 1) * 16;
    // V (trans): row = k-half * 8 + lr (key dim), colbyte = n-half * 16 (dh dim)
    uint32_t voff = ((sel & 1) * 8 + lr) * ALD + (sel >> 1) * 16;

    for (int mt = w; mt < 13; mt += 7) {
        int m0 = mt * 16;
        int r0 = min(m0 + gr, Pp - 1);
        int r1 = min(m0 + gr + 8, Pp - 1);

        // ---- Q fragments from gmem
        uint32_t qa_h[4][4], qa_l[4][4];
        #pragma unroll
        for (int J = 0; J < 4; J++) {
            int c0 = J * 16 + qc;
            qa_h[J][0] = *(const uint32_t*)&g_qh[qbase + (size_t)r0 * Dd + c0];
            qa_h[J][1] = *(const uint32_t*)&g_qh[qbase + (size_t)r1 * Dd + c0];
            qa_h[J][2] = *(const uint32_t*)&g_qh[qbase + (size_t)r0 * Dd + c0 + 8];
            qa_h[J][3] = *(const uint32_t*)&g_qh[qbase + (size_t)r1 * Dd + c0 + 8];
            qa_l[J][0] = *(const uint32_t*)&g_ql[qbase + (size_t)r0 * Dd + c0];
            qa_l[J][1] = *(const uint32_t*)&g_ql[qbase + (size_t)r1 * Dd + c0];
            qa_l[J][2] = *(const uint32_t*)&g_ql[qbase + (size_t)r0 * Dd + c0 + 8];
            qa_l[J][3] = *(const uint32_t*)&g_ql[qbase + (size_t)r1 * Dd + c0 + 8];
        }

        // ---- S = Q K^T : sc[26][4]
        float sc[26][4];
        #pragma unroll
        for (int nt = 0; nt < 26; nt++)
            #pragma unroll
            for (int i = 0; i < 4; i++) sc[nt][i] = 0.f;

        for (int ntp = 0; ntp < 13; ntp++) {
            uint32_t kb = ntp * (16 * ALD) + koff;
            #pragma unroll
            for (int J = 0; J < 4; J++) {
                uint32_t bh[4], bl[4];
                ldsm4(bh, skh + kb + J * 32);
                ldsm4(bl, skl + kb + J * 32);
                mma_bf16(sc[2*ntp],   qa_h[J], bh[0], bh[1]);
                mma_bf16(sc[2*ntp],   qa_h[J], bl[0], bl[1]);
                mma_bf16(sc[2*ntp],   qa_l[J], bh[0], bh[1]);
                mma_bf16(sc[2*ntp+1], qa_h[J], bh[2], bh[3]);
                mma_bf16(sc[2*ntp+1], qa_h[J], bl[2], bl[3]);
                mma_bf16(sc[2*ntp+1], qa_l[J], bh[2], bh[3]);
            }
        }

        // ---- softmax (registers, 4-lane row groups)
        float mx0 = -1e30f, mx1 = -1e30f;
        #pragma unroll
        for (int nt = 0; nt < 26; nt++) {
            int n0 = nt * 8 + qc;
            if (n0 >= Pp) {
                sc[nt][0] = sc[nt][1] = sc[nt][2] = sc[nt][3] = -1e30f;
            } else {
                sc[nt][0] *= 0.125f; sc[nt][1] *= 0.125f;
                sc[nt][2] *= 0.125f; sc[nt][3] *= 0.125f;
            }
            mx0 = fmaxf(mx0, fmaxf(sc[nt][0], sc[nt][1]));
            mx1 = fmaxf(mx1, fmaxf(sc[nt][2], sc[nt][3]));
        }
        mx0 = fmaxf(mx0, __shfl_xor_sync(0xffffffffu, mx0, 1));
        mx0 = fmaxf(mx0, __shfl_xor_sync(0xffffffffu, mx0, 2));
        mx1 = fmaxf(mx1, __shfl_xor_sync(0xffffffffu, mx1, 1));
        mx1 = fmaxf(mx1, __shfl_xor_sync(0xffffffffu, mx1, 2));
        float sum0 = 0.f, sum1 = 0.f;
        #pragma unroll
        for (int nt = 0; nt < 26; nt++) {
            sc[nt][0] = __expf(sc[nt][0] - mx0);
            sc[nt][1] = __expf(sc[nt][1] - mx0);
            sc[nt][2] = __expf(sc[nt][2] - mx1);
            sc[nt][3] = __expf(sc[nt][3] - mx1);
            sum0 += sc[nt][0] + sc[nt][1];
            sum1 += sc[nt][2] + sc[nt][3];
        }
        sum0 += __shfl_xor_sync(0xffffffffu, sum0, 1);
        sum0 += __shfl_xor_sync(0xffffffffu, sum0, 2);
        sum1 += __shfl_xor_sync(0xffffffffu, sum1, 1);
        sum1 += __shfl_xor_sync(0xffffffffu, sum1, 2);
        float rv0 = 1.0f / sum0, rv1 = 1.0f / sum1;
        #pragma unroll
        for (int nt = 0; nt < 26; nt++) {
            sc[nt][0] *= rv0; sc[nt][1] *= rv0;
            sc[nt][2] *= rv1; sc[nt][3] *= rv1;
        }

        // ---- O = P V : oacc[8][4]
        float oacc[8][4];
        #pragma unroll
        for (int i = 0; i < 8; i++)
            #pragma unroll
            for (int jx = 0; jx < 4; jx++) oacc[i][jx] = 0.f;

        for (int J = 0; J < 13; J++) {
            uint32_t pa_h[4], pa_l[4];
            {
                float p00 = sc[2*J][0],   p01 = sc[2*J][1];
                float p10 = sc[2*J][2],   p11 = sc[2*J][3];
                float p20 = sc[2*J+1][0], p21 = sc[2*J+1][1];
                float p30 = sc[2*J+1][2], p31 = sc[2*J+1][3];
                __nv_bfloat16 hh;
                float l00, l01, l10, l11, l20, l21, l30, l31;
                hh = __float2bfloat16(p00); l00 = p00 - __bfloat162float(hh);
                hh = __float2bfloat16(p01); l01 = p01 - __bfloat162float(hh);
                hh = __float2bfloat16(p10); l10 = p10 - __bfloat162float(hh);
                hh = __float2bfloat16(p11); l11 = p11 - __bfloat162float(hh);
                hh = __float2bfloat16(p20); l20 = p20 - __bfloat162float(hh);
                hh = __float2bfloat16(p21); l21 = p21 - __bfloat162float(hh);
                hh = __float2bfloat16(p30); l30 = p30 - __bfloat162float(hh);
                hh = __float2bfloat16(p31); l31 = p31 - __bfloat162float(hh);
                pa_h[0] = pack_bf16(p00, p01);
                pa_h[1] = pack_bf16(p10, p11);
                pa_h[2] = pack_bf16(p20, p21);
                pa_h[3] = pack_bf16(p30, p31);
                pa_l[0] = pack_bf16(l00, l01);
                pa_l[1] = pack_bf16(l10, l11);
                pa_l[2] = pack_bf16(l20, l21);
                pa_l[3] = pack_bf16(l30, l31);
            }
            uint32_t vb = J * (16 * ALD) + voff;
            #pragma unroll
            for (int np = 0; np < 4; np++) {
                uint32_t bh[4], bl[4];
                ldsm4t(bh, svh + vb + np * 32);
                ldsm4t(bl, svl + vb + np * 32);
                mma_bf16(oacc[2*np],   pa_h, bh[0], bh[1]);
                mma_bf16(oacc[2*np],   pa_h, bl[0], bl[1]);
                mma_bf16(oacc[2*np],   pa_l, bh[0], bh[1]);
                mma_bf16(oacc[2*np+1], pa_h, bh[2], bh[3]);
                mma_bf16(oacc[2*np+1], pa_h, bl[2], bl[3]);
                mma_bf16(oacc[2*np+1], pa_l, bh[2], bh[3]);
            }
        }

        // ---- store O
        int p0r = m0 + gr, p1r = m0 + gr + 8;
        #pragma unroll
        for (int nt2 = 0; nt2 < 8; nt2++) {
            int n = nt2 * 8 + qc;
            if (p0r < Pp)
                *(float2*)&Ob[(size_t)p0r * Dd + n] = make_float2(oacc[nt2][0], oacc[nt2][1]);
            if (p1r < Pp)
                *(float2*)&Ob[(size_t)p1r * Dd + n] = make_float2(oacc[nt2][2], oacc[nt2][3]);
        }
    }
}

// ---------------- launch ----------------
extern "C" void kernel_launch(void* const* d_in, const int* in_sizes, int n_in,
                              void* d_out, int out_size) {
    const float* x    = (const float*)d_in[0];
    const float* Wq   = (const float*)d_in[1];
    const float* bq   = (const float*)d_in[2];
    const float* Wk   = (const float*)d_in[3];
    const float* bk   = (const float*)d_in[4];
    const float* Wv   = (const float*)d_in[5];
    const float* bv   = (const float*)d_in[6];
    const float* in_a = (const float*)d_in[7];
    const float* in_b = (const float*)d_in[8];
    const float* at_a = (const float*)d_in[9];
    const float* at_b = (const float*)d_in[10];
    const float* ou_a = (const float*)d_in[11];
    const float* ou_b = (const float*)d_in[12];
    const float* Wt   = (const float*)d_in[13];
    const float* bt   = (const float*)d_in[14];
    const float* pos  = (const float*)d_in[15];
    const float* W1   = (const float*)d_in[16];
    const float* b1   = (const float*)d_in[17];
    const float* W2   = (const float*)d_in[18];
    const float* b2   = (const float*)d_in[19];

    float *pav, *pxres, *pbtsum;
    __nv_bfloat16 *px2h, *px2l, *pyh, *pyl, *phh, *phl, *pwh, *pwl;
    __nv_bfloat16 *pqh, *pql, *pkh, *pkl, *pvh, *pvl;
    cudaGetSymbolAddress((void**)&pav,  g_av);
    cudaGetSymbolAddress((void**)&pxres,g_xres);
    cudaGetSymbolAddress((void**)&pbtsum, g_btsum);
    cudaGetSymbolAddress((void**)&px2h, g_x2h);
    cudaGetSymbolAddress((void**)&px2l, g_x2l);
    cudaGetSymbolAddress((void**)&pyh,  g_yh);
    cudaGetSymbolAddress((void**)&pyl,  g_yl);
    cudaGetSymbolAddress((void**)&phh,  g_hh);
    cudaGetSymbolAddress((void**)&phl,  g_hl);
    cudaGetSymbolAddress((void**)&pwh,  w_hi);
    cudaGetSymbolAddress((void**)&pwl,  w_lo);
    cudaGetSymbolAddress((void**)&pqh,  g_qh);
    cudaGetSymbolAddress((void**)&pql,  g_ql);
    cudaGetSymbolAddress((void**)&pkh,  g_kh);
    cudaGetSymbolAddress((void**)&pkl,  g_kl);
    cudaGetSymbolAddress((void**)&pvh,  g_vh);
    cudaGetSymbolAddress((void**)&pvl,  g_vl);

    cudaFuncSetAttribute(attn_mma_k, cudaFuncAttributeMaxDynamicSharedMemorySize,
                         ATT_SMEM);
    cudaFuncSetAttribute(gemm_mma_k, cudaFuncAttributeMaxDynamicSharedMemorySize,
                         GM_SMEM);

    // weight conversions
    wcvt_k<<<(262144 + 255) / 256, 256>>>(Wq, pwh + OQ,  pwl + OQ,  262144);
    wcvt_k<<<(262144 + 255) / 256, 256>>>(Wk, pwh + OKo, pwl + OKo, 262144);
    wcvt_k<<<(262144 + 255) / 256, 256>>>(Wv, pwh + OV,  pwl + OV,  262144);
    wcvt_k<<<(3145728 + 255) / 256, 256>>>(Wt, pwh + OT, pwl + OT, 3145728);
    wcvt_k<<<(524288 + 255) / 256, 256>>>(W1, pwh + O1,  pwl + O1,  524288);
    wcvt_k<<<(524288 + 255) / 256, 256>>>(W2, pwh + O2,  pwl + O2,  524288);
    btsum_k<<<2, 256>>>(bt);

    // LN(x) -> x2 hi/lo
    ln_bf_k<<<M1, 256>>>(x, in_a, in_b, nullptr, px2h, px2l, 1);

    // QKV projections (mode 4: bf16 hi/lo out)
    dim3 gqkv(Dd / 128, (M1 + 127) / 128);
    gemm_mma_k<<<gqkv, 256, GM_SMEM>>>(px2h, px2l, pwh + OQ,  pwl + OQ,  bq, nullptr, nullptr, pqh, pql, M1, Dd, Dd, 4);
    gemm_mma_k<<<gqkv, 256, GM_SMEM>>>(px2h, px2l, pwh + OKo, pwl + OKo, bk, nullptr, nullptr, pkh, pkl, M1, Dd, Dd, 4);
    gemm_mma_k<<<gqkv, 256, GM_SMEM>>>(px2h, px2l, pwh + OV,  pwl + OV,  bv, nullptr, nullptr, pvh, pvl, M1, Dd, Dd, 4);

    // tensor-core attention -> g_av (fp32)
    attn_mma_k<<<Bq * Tt * Tt * Hh, 224, ATT_SMEM>>>();

    // LN(av)+pos -> y hi/lo
    ln_bf_k<<<ROWS_AV, 256>>>(pav, at_a, at_b, pos, pyh, pyl, POSMOD);

    // tc contraction (mode 1)
    gemm_mma_k<<<gqkv, 256, GM_SMEM>>>(pyh, pyl, pwh + OT, pwl + OT, pbtsum, x, pxres, nullptr, nullptr, M1, Dd, Tt * Dd, 1);

    // LN(xres) -> x2 hi/lo
    ln_bf_k<<<M1, 256>>>(pxres, ou_a, ou_b, nullptr, px2h, px2l, 1);

    // MLP1 (mode 2) -> h hi/lo
    dim3 g1(2 * Dd / 128, (M1 + 127) / 128);
    gemm_mma_k<<<g1, 256, GM_SMEM>>>(px2h, px2l, pwh + O1, pwl + O1, b1, nullptr, nullptr, phh, phl, M1, 2 * Dd, Dd, 2);

    // MLP2 (mode 3) -> d_out
    gemm_mma_k<<<gqkv, 256, GM_SMEM>>>(phh, phl, pwh + O2, pwl + O2, b2, pxres, (float*)d_out, nullptr, nullptr, M1, Dd, 2 * Dd, 3);
}

// round 7
// speedup vs baseline: 4.2147x; 1.0576x over previous
#include <cuda_runtime.h>
#include <cuda_bf16.h>
#include <math.h>
#include <stdint.h>

#define Bq 4
#define Tt 12
#define Pp 196
#define Dd 512
#define Hh 8
#define DHd 64
#define EPSV 1e-6f

#define M1 (Bq*Tt*Pp)            // 9408
#define ROWS_AV (Bq*Tt*Tt*Pp)    // 112896
#define POSMOD (Tt*Tt*Pp)        // 28224

// weight offsets in converted buffer
#define OQ 0
#define OKo 262144
#define OV  524288
#define OT  786432
#define O1  3932160
#define O2  4456448
#define WTOT 4980736

// ---------------- scratch ----------------
__device__ float g_av[(size_t)ROWS_AV*Dd];
__device__ float g_xres[M1*Dd];
__device__ float g_btsum[Dd];
__device__ float g_bqkv[3*Dd];
__device__ __nv_bfloat16 g_x2h[M1*Dd],  g_x2l[M1*Dd];
__device__ __nv_bfloat16 g_qh[M1*Dd], g_ql[M1*Dd];
__device__ __nv_bfloat16 g_kh[M1*Dd], g_kl[M1*Dd];
__device__ __nv_bfloat16 g_vh[M1*Dd], g_vl[M1*Dd];
__device__ __nv_bfloat16 g_yh[(size_t)ROWS_AV*Dd], g_yl[(size_t)ROWS_AV*Dd];
__device__ __nv_bfloat16 g_hh[M1*2*Dd], g_hl[M1*2*Dd];
__device__ __nv_bfloat16 w_hi[WTOT], w_lo[WTOT];

// ---------------- helpers ----------------
__device__ __forceinline__ float gelu_exact(float x) {
    return 0.5f * x * (1.0f + erff(x * 0.70710678118654752f));
}
__device__ __forceinline__ uint32_t smem_u32(const void* p) {
    uint32_t a;
    asm("{ .reg .u64 t; cvta.to.shared.u64 t, %1; cvt.u32.u64 %0, t; }" : "=r"(a) : "l"(p));
    return a;
}
__device__ __forceinline__ void ldsm4(uint32_t* r, uint32_t a) {
    asm volatile("ldmatrix.sync.aligned.m8n8.x4.shared.b16 {%0,%1,%2,%3}, [%4];"
                 : "=r"(r[0]), "=r"(r[1]), "=r"(r[2]), "=r"(r[3]) : "r"(a));
}
__device__ __forceinline__ void ldsm4t(uint32_t* r, uint32_t a) {
    asm volatile("ldmatrix.sync.aligned.m8n8.x4.trans.shared.b16 {%0,%1,%2,%3}, [%4];"
                 : "=r"(r[0]), "=r"(r[1]), "=r"(r[2]), "=r"(r[3]) : "r"(a));
}
__device__ __forceinline__ void mma_bf16(float* c, const uint32_t* a, uint32_t b0, uint32_t b1) {
    asm volatile(
        "mma.sync.aligned.m16n8k16.row.col.f32.bf16.bf16.f32 "
        "{%0,%1,%2,%3}, {%4,%5,%6,%7}, {%8,%9}, {%0,%1,%2,%3};"
        : "+f"(c[0]), "+f"(c[1]), "+f"(c[2]), "+f"(c[3])
        : "r"(a[0]), "r"(a[1]), "r"(a[2]), "r"(a[3]), "r"(b0), "r"(b1));
}
__device__ __forceinline__ void cpa16(uint32_t s, const void* g) {
    asm volatile("cp.async.cg.shared.global [%0], [%1], 16;" :: "r"(s), "l"(g));
}
#define CPA_COMMIT() asm volatile("cp.async.commit_group;" ::: "memory")
#define CPA_WAIT(n)  asm volatile("cp.async.wait_group %0;" :: "n"(n) : "memory")

__device__ __forceinline__ uint32_t pack_bf16(float a, float b) {
    __nv_bfloat162 t = __floats2bfloat162_rn(a, b);
    return *(uint32_t*)&t;
}

// ---------------- bt sum ----------------
__global__ void btsum_k(const float* __restrict__ bt) {
    int e = blockIdx.x * blockDim.x + threadIdx.x;
    if (e < Dd) {
        float s = 0.f;
        #pragma unroll
        for (int u = 0; u < Tt; u++) s += bt[u * Dd + e];
        g_btsum[e] = s;
    }
}

// ---------------- QKV weight + bias convert (one launch) ----------------
__global__ void wcvt_qkv_k(const float* __restrict__ Wq, const float* __restrict__ Wk,
                           const float* __restrict__ Wv,
                           const float* __restrict__ bq, const float* __restrict__ bk,
                           const float* __restrict__ bv) {
    int i = blockIdx.x * 256 + threadIdx.x;
    if (i < 3 * Dd)
        g_bqkv[i] = (i < Dd) ? bq[i] : (i < 2 * Dd) ? bk[i - Dd] : bv[i - 2 * Dd];
    if (i < 786432) {
        int seg = i >> 18, off = i & 262143;
        float v = (seg == 0) ? Wq[off] : (seg == 1) ? Wk[off] : Wv[off];
        __nv_bfloat16 h = __float2bfloat16(v);
        w_hi[i] = h;
        w_lo[i] = __float2bfloat16(v - __bfloat162float(h));
    }
}

// ---------------- Wt/W1/W2 convert (one launch, after attn) ----------------
__global__ void wcvt_rest_k(const float* __restrict__ Wt, const float* __restrict__ W1,
                            const float* __restrict__ W2) {
    int i = blockIdx.x * 256 + threadIdx.x;  // < 4194304
    float v; int di;
    if (i < 3145728)      { v = Wt[i];            di = OT + i; }
    else if (i < 3670016) { v = W1[i - 3145728];  di = O1 + (i - 3145728); }
    else                  { v = W2[i - 3670016];  di = O2 + (i - 3670016); }
    __nv_bfloat16 h = __float2bfloat16(v);
    w_hi[di] = h;
    w_lo[di] = __float2bfloat16(v - __bfloat162float(h));
}

// ---------------- LayerNorm: warp-per-row -> bf16 hi/lo (+pos) ----------------
__global__ void ln_bf_k(const float* __restrict__ in,
                        const float* __restrict__ al,
                        const float* __restrict__ be,
                        const float* __restrict__ pos,
                        __nv_bfloat16* __restrict__ oh,
                        __nv_bfloat16* __restrict__ ol,
                        int posmod) {
    int w = threadIdx.x >> 5, lane = threadIdx.x & 31;
    int row = blockIdx.x * 8 + w;
    const float* rp = in + (size_t)row * Dd;
    float4 v[4];
    float s = 0.f, sq = 0.f;
    #pragma unroll
    for (int j = 0; j < 4; j++) {
        v[j] = *(const float4*)&rp[lane * 4 + j * 128];
        s  += v[j].x + v[j].y + v[j].z + v[j].w;
        sq += v[j].x*v[j].x + v[j].y*v[j].y + v[j].z*v[j].z + v[j].w*v[j].w;
    }
    #pragma unroll
    for (int o = 16; o; o >>= 1) {
        s  += __shfl_xor_sync(0xffffffffu, s,  o);
        sq += __shfl_xor_sync(0xffffffffu, sq, o);
    }
    float mu  = s * (1.0f / Dd);
    float var = (sq - (float)Dd * mu * mu) * (1.0f / (Dd - 1));
    float inv = 1.0f / (sqrtf(fmaxf(var, 0.f)) + EPSV);
    const float* pp = pos ? (pos + (size_t)(row % posmod) * Dd) : nullptr;

    #pragma unroll
    for (int j = 0; j < 4; j++) {
        int c = lane * 4 + j * 128;
        float4 a = *(const float4*)&al[c];
        float4 b = *(const float4*)&be[c];
        float o0 = a.x * (v[j].x - mu) * inv + b.x;
        float o1 = a.y * (v[j].y - mu) * inv + b.y;
        float o2 = a.z * (v[j].z - mu) * inv + b.z;
        float o3 = a.w * (v[j].w - mu) * inv + b.w;
        if (pp) {
            float4 p = *(const float4*)&pp[c];
            o0 += p.x; o1 += p.y; o2 += p.z; o3 += p.w;
        }
        __nv_bfloat16 h0 = __float2bfloat16(o0);
        __nv_bfloat16 h1 = __float2bfloat16(o1);
        __nv_bfloat16 h2 = __float2bfloat16(o2);
        __nv_bfloat16 h3 = __float2bfloat16(o3);
        uint2 hv, lv;
        hv.x = pack_bf16(__bfloat162float(h0), __bfloat162float(h1));
        hv.y = pack_bf16(__bfloat162float(h2), __bfloat162float(h3));
        // pack exact hi bits instead: rebuild from h's
        __nv_bfloat162 hh01 = __nv_bfloat162(h0, h1);
        __nv_bfloat162 hh23 = __nv_bfloat162(h2, h3);
        hv.x = *(uint32_t*)&hh01;
        hv.y = *(uint32_t*)&hh23;
        __nv_bfloat162 ll01 = __floats2bfloat162_rn(o0 - __bfloat162float(h0),
                                                    o1 - __bfloat162float(h1));
        __nv_bfloat162 ll23 = __floats2bfloat162_rn(o2 - __bfloat162float(h2),
                                                    o3 - __bfloat162float(h3));
        lv.x = *(uint32_t*)&ll01;
        lv.y = *(uint32_t*)&ll23;
        *(uint2*)&oh[(size_t)row * Dd + c] = hv;
        *(uint2*)&ol[(size_t)row * Dd + c] = lv;
    }
}

// ================= mma.sync bf16x3 GEMM ======================
// modes: 0: Cf = acc + bias
//        1 (tc): Cf = res + gelu(acc/12 + bias); A is [b,t,u,p,d], B per-u
//        2: Chi/Clo = split(gelu(acc + bias))
//        3: Cf = res + gelu(acc + bias)
//        4: Chi/Clo = split(acc + bias)
//        5 (qkv): split(acc + bias) routed to g_q/g_k/g_v hi/lo by n>>9
#define LDSE 72
#define TILE_B (128*LDSE*2)
#define STAGE_B (4*TILE_B)
#define GM_SMEM (2*STAGE_B)

__global__ void __launch_bounds__(256, 1) gemm_mma_k(
    const __nv_bfloat16* __restrict__ Ahi, const __nv_bfloat16* __restrict__ Alo,
    const __nv_bfloat16* __restrict__ Bhi, const __nv_bfloat16* __restrict__ Blo,
    const float* __restrict__ bias, const float* __restrict__ res,
    float* __restrict__ Cf, __nv_bfloat16* __restrict__ Chi, __nv_bfloat16* __restrict__ Clo,
    int M, int N, int K, int mode)
{
    extern __shared__ char smc[];
    int tid = threadIdx.x;
    int wid = tid >> 5, lane = tid & 31;
    int bm = blockIdx.y * 128, bn = blockIdx.x * 128;
    int wm = (wid >> 2) * 64;
    int wn = (wid & 3) * 32;

    int lrow = tid >> 1;
    int lhalf = tid & 1;
    int am = min(bm + lrow, M - 1);
    size_t abase;
    if (mode == 1) {
        int b_ = am / (Tt * Pp), r_ = am % (Tt * Pp);
        int t_ = r_ / Pp, p_ = r_ % Pp;
        abase = ((size_t)(b_ * (Tt * Tt) + t_ * Tt) * Pp + p_) * Dd;
    } else {
        abase = (size_t)am * K;
    }
    int brow = bn + lrow;
    uint32_t smrow = lrow * (LDSE * 2);

    int NC = K / 64;

    auto load_stage = [&](int buf, int c) {
        size_t aoff, boff;
        if (mode == 1) {
            int u = c >> 3, d0 = (c & 7) * 64;
            aoff = abase + (size_t)u * (Pp * Dd) + d0;
            boff = (size_t)u * (Dd * Dd) + (size_t)brow * Dd + d0;
        } else {
            aoff = abase + c * 64;
            boff = (size_t)brow * K + c * 64;
        }
        uint32_t sb = smem_u32(smc) + buf * STAGE_B + smrow;
        #pragma unroll
        for (int i = 0; i < 4; i++) {
            int colk = lhalf * 32 + i * 8;
            uint32_t so = sb + colk * 2;
            cpa16(so,              Ahi + aoff + colk);
            cpa16(so + TILE_B,     Alo + aoff + colk);
            cpa16(so + 2*TILE_B,   Bhi + boff + colk);
            cpa16(so + 3*TILE_B,   Blo + boff + colk);
        }
    };

    int sel = lane >> 3, lr = lane & 7;
    int a_m = wm + (sel & 1) * 8 + lr;
    int a_k = (sel >> 1) * 8;
    int b_n = wn + (sel >> 1) * 8 + lr;
    int b_k = (sel & 1) * 8;
    uint32_t smb = smem_u32(smc);
    uint32_t aoffB = (a_m * LDSE + a_k) * 2;
    uint32_t boffB = (b_n * LDSE + b_k) * 2;

    float acc[4][4][4] = {};

    load_stage(0, 0);
    CPA_COMMIT();

    for (int c = 0; c < NC; c++) {
        int buf = c & 1;
        if (c + 1 < NC) {
            load_stage(buf ^ 1, c + 1);
            CPA_COMMIT();
            CPA_WAIT(1);
        } else {
            CPA_WAIT(0);
        }
        __syncthreads();

        uint32_t base = smb + buf * STAGE_B;
        uint32_t aHb = base + aoffB;
        uint32_t aLb = aHb + TILE_B;
        uint32_t bHb = base + 2*TILE_B + boffB;
        uint32_t bLb = bHb + TILE_B;

        #pragma unroll
        for (int kk = 0; kk < 4; kk++) {
            uint32_t ko = kk * 32;
            uint32_t aH[4][4], aL[4][4], bH[2][4], bL[2][4];
            #pragma unroll
            for (int mt = 0; mt < 4; mt++) {
                ldsm4(aH[mt], aHb + mt * (16 * LDSE * 2) + ko);
                ldsm4(aL[mt], aLb + mt * (16 * LDSE * 2) + ko);
            }
            #pragma unroll
            for (int nt2 = 0; nt2 < 2; nt2++) {
                ldsm4(bH[nt2], bHb + nt2 * (16 * LDSE * 2) + ko);
                ldsm4(bL[nt2], bLb + nt2 * (16 * LDSE * 2) + ko);
            }
            #pragma unroll
            for (int mt = 0; mt < 4; mt++) {
                #pragma unroll
                for (int nt = 0; nt < 4; nt++) {
                    int s2 = nt >> 1, pp = (nt & 1) * 2;
                    mma_bf16(acc[mt][nt], aH[mt], bH[s2][pp], bH[s2][pp+1]);
                    mma_bf16(acc[mt][nt], aH[mt], bL[s2][pp], bL[s2][pp+1]);
                    mma_bf16(acc[mt][nt], aL[mt], bH[s2][pp], bH[s2][pp+1]);
                }
            }
        }
        __syncthreads();
    }

    int qrow = lane >> 2;
    int qcol = (lane & 3) * 2;
    #pragma unroll
    for (int mt = 0; mt < 4; mt++) {
        #pragma unroll
        for (int nt = 0; nt < 4; nt++) {
            float* cc = acc[mt][nt];
            int n0 = bn + wn + nt * 8 + qcol;
            float b0 = bias[n0], b1 = bias[n0 + 1];
            #pragma unroll
            for (int hrow = 0; hrow < 2; hrow++) {
                int m = bm + wm + mt * 16 + qrow + hrow * 8;
                if (m >= M) continue;
                float a0 = cc[hrow * 2 + 0];
                float a1 = cc[hrow * 2 + 1];
                float v0, v1;
                if (mode == 0) {
                    size_t off = (size_t)m * N + n0;
                    v0 = a0 + b0; v1 = a1 + b1;
                    *(float2*)&Cf[off] = make_float2(v0, v1);
                } else if (mode == 1) {
                    size_t off = (size_t)m * N + n0;
                    float2 r = *(const float2*)&res[off];
                    v0 = r.x + gelu_exact(a0 * (1.0f / Tt) + b0);
                    v1 = r.y + gelu_exact(a1 * (1.0f / Tt) + b1);
                    *(float2*)&Cf[off] = make_float2(v0, v1);
                } else if (mode == 3) {
                    size_t off = (size_t)m * N + n0;
                    float2 r = *(const float2*)&res[off];
                    v0 = r.x + gelu_exact(a0 + b0);
                    v1 = r.y + gelu_exact(a1 + b1);
                    *(float2*)&Cf[off] = make_float2(v0, v1);
                } else if (mode == 5) {
                    int seg = n0 >> 9, nn = n0 & 511;
                    __nv_bfloat16* dh = (seg == 0) ? g_qh : (seg == 1) ? g_kh : g_vh;
                    __nv_bfloat16* dl = (seg == 0) ? g_ql : (seg == 1) ? g_kl : g_vl;
                    float g0 = a0 + b0, g1 = a1 + b1;
                    __nv_bfloat16 h0 = __float2bfloat16(g0);
                    __nv_bfloat16 h1 = __float2bfloat16(g1);
                    __nv_bfloat162 hh = __nv_bfloat162(h0, h1);
                    __nv_bfloat162 ll = __floats2bfloat162_rn(g0 - __bfloat162float(h0),
                                                              g1 - __bfloat162float(h1));
                    size_t off = (size_t)m * Dd + nn;
                    *(__nv_bfloat162*)(dh + off) = hh;
                    *(__nv_bfloat162*)(dl + off) = ll;
                } else { // mode 2 or 4
                    size_t off = (size_t)m * N + n0;
                    float g0 = (mode == 2) ? gelu_exact(a0 + b0) : (a0 + b0);
                    float g1 = (mode == 2) ? gelu_exact(a1 + b1) : (a1 + b1);
                    __nv_bfloat16 h0 = __float2bfloat16(g0);
                    __nv_bfloat16 h1 = __float2bfloat16(g1);
                    __nv_bfloat162 hh = __nv_bfloat162(h0, h1);
                    __nv_bfloat162 ll = __floats2bfloat162_rn(g0 - __bfloat162float(h0),
                                                              g1 - __bfloat162float(h1));
                    *(__nv_bfloat162*)(Chi + off) = hh;
                    *(__nv_bfloat162*)(Clo + off) = ll;
                }
            }
        }
    }
}

// ================= tensor-core attention (bf16x3) ======================
// one block per (b,t,u,h); 8 warps; M-tiles of 16 queries (13 tiles).
// K and V both row-major [208][72] bf16 hi/lo in smem (144B rows).
// QK^T uses non-trans ldmatrix on K; PV uses ldmatrix.trans on V.
#define AKR 208
#define ALD 144
#define ASM_ONE (AKR*ALD)              // 29952 bytes
#define ATT_SMEM (4*ASM_ONE)           // 119808

__global__ void __launch_bounds__(256, 1) attn_mma_k() {
    int bid = blockIdx.x;
    int h = bid & 7;
    int u = (bid >> 3) % Tt;
    int t = (bid / (Hh * Tt)) % Tt;
    int b = bid / (Hh * Tt * Tt);

    extern __shared__ char smb_[];
    uint32_t skh = smem_u32(smb_);
    uint32_t skl = skh + ASM_ONE;
    uint32_t svh = skh + 2 * ASM_ONE;
    uint32_t svl = skh + 3 * ASM_ONE;

    int tid = threadIdx.x;
    int w = tid >> 5, lane = tid & 31;

    size_t kvbase = ((size_t)(b * Tt + u) * Pp) * Dd + h * DHd;
    size_t qbase  = ((size_t)(b * Tt + t) * Pp) * Dd + h * DHd;
    float* Ob = g_av + ((size_t)((b * Tt + t) * Tt + u) * Pp) * Dd + h * DHd;

    for (int idx = tid; idx < AKR * 8; idx += 256) {
        int row = idx >> 3, seg = idx & 7;
        uint4 kh4 = make_uint4(0,0,0,0), kl4 = kh4, vh4 = kh4, vl4 = kh4;
        if (row < Pp) {
            size_t g = kvbase + (size_t)row * Dd + seg * 8;
            kh4 = *(const uint4*)&g_kh[g];
            kl4 = *(const uint4*)&g_kl[g];
            vh4 = *(const uint4*)&g_vh[g];
            vl4 = *(const uint4*)&g_vl[g];
        }
        uint32_t so = row * ALD + seg * 16;
        *(uint4*)(smb_ + so) = kh4;
        *(uint4*)(smb_ + ASM_ONE + so) = kl4;
        *(uint4*)(smb_ + 2*ASM_ONE + so) = vh4;
        *(uint4*)(smb_ + 3*ASM_ONE + so) = vl4;
    }
    __syncthreads();

    int gr = lane >> 2, qc = (lane & 3) * 2;
    int sel = lane >> 3, lr = lane & 7;
    uint32_t koff = ((sel >> 1) * 8 + lr) * ALD + (sel & 1) * 16;
    uint32_t voff = ((sel & 1) * 8 + lr) * ALD + (sel >> 1) * 16;

    for (int mt = w; mt < 13; mt += 8) {
        int m0 = mt * 16;
        int r0 = min(m0 + gr, Pp - 1);
        int r1 = min(m0 + gr + 8, Pp - 1);

        uint32_t qa_h[4][4], qa_l[4][4];
        #pragma unroll
        for (int J = 0; J < 4; J++) {
            int c0 = J * 16 + qc;
            qa_h[J][0] = *(const uint32_t*)&g_qh[qbase + (size_t)r0 * Dd + c0];
            qa_h[J][1] = *(const uint32_t*)&g_qh[qbase + (size_t)r1 * Dd + c0];
            qa_h[J][2] = *(const uint32_t*)&g_qh[qbase + (size_t)r0 * Dd + c0 + 8];
            qa_h[J][3] = *(const uint32_t*)&g_qh[qbase + (size_t)r1 * Dd + c0 + 8];
            qa_l[J][0] = *(const uint32_t*)&g_ql[qbase + (size_t)r0 * Dd + c0];
            qa_l[J][1] = *(const uint32_t*)&g_ql[qbase + (size_t)r1 * Dd + c0];
            qa_l[J][2] = *(const uint32_t*)&g_ql[qbase + (size_t)r0 * Dd + c0 + 8];
            qa_l[J][3] = *(const uint32_t*)&g_ql[qbase + (size_t)r1 * Dd + c0 + 8];
        }

        float sc[26][4];
        #pragma unroll
        for (int nt = 0; nt < 26; nt++)
            #pragma unroll
            for (int i = 0; i < 4; i++) sc[nt][i] = 0.f;

        for (int ntp = 0; ntp < 13; ntp++) {
            uint32_t kb = ntp * (16 * ALD) + koff;
            #pragma unroll
            for (int J = 0; J < 4; J++) {
                uint32_t bh[4], bl[4];
                ldsm4(bh, skh + kb + J * 32);
                ldsm4(bl, skl + kb + J * 32);
                mma_bf16(sc[2*ntp],   qa_h[J], bh[0], bh[1]);
                mma_bf16(sc[2*ntp],   qa_h[J], bl[0], bl[1]);
                mma_bf16(sc[2*ntp],   qa_l[J], bh[0], bh[1]);
                mma_bf16(sc[2*ntp+1], qa_h[J], bh[2], bh[3]);
                mma_bf16(sc[2*ntp+1], qa_h[J], bl[2], bl[3]);
                mma_bf16(sc[2*ntp+1], qa_l[J], bh[2], bh[3]);
            }
        }

        float mx0 = -1e30f, mx1 = -1e30f;
        #pragma unroll
        for (int nt = 0; nt < 26; nt++) {
            int n0 = nt * 8 + qc;
            if (n0 >= Pp) {
                sc[nt][0] = sc[nt][1] = sc[nt][2] = sc[nt][3] = -1e30f;
            } else {
                sc[nt][0] *= 0.125f; sc[nt][1] *= 0.125f;
                sc[nt][2] *= 0.125f; sc[nt][3] *= 0.125f;
            }
            mx0 = fmaxf(mx0, fmaxf(sc[nt][0], sc[nt][1]));
            mx1 = fmaxf(mx1, fmaxf(sc[nt][2], sc[nt][3]));
        }
        mx0 = fmaxf(mx0, __shfl_xor_sync(0xffffffffu, mx0, 1));
        mx0 = fmaxf(mx0, __shfl_xor_sync(0xffffffffu, mx0, 2));
        mx1 = fmaxf(mx1, __shfl_xor_sync(0xffffffffu, mx1, 1));
        mx1 = fmaxf(mx1, __shfl_xor_sync(0xffffffffu, mx1, 2));
        float sum0 = 0.f, sum1 = 0.f;
        #pragma unroll
        for (int nt = 0; nt < 26; nt++) {
            sc[nt][0] = __expf(sc[nt][0] - mx0);
            sc[nt][1] = __expf(sc[nt][1] - mx0);
            sc[nt][2] = __expf(sc[nt][2] - mx1);
            sc[nt][3] = __expf(sc[nt][3] - mx1);
            sum0 += sc[nt][0] + sc[nt][1];
            sum1 += sc[nt][2] + sc[nt][3];
        }
        sum0 += __shfl_xor_sync(0xffffffffu, sum0, 1);
        sum0 += __shfl_xor_sync(0xffffffffu, sum0, 2);
        sum1 += __shfl_xor_sync(0xffffffffu, sum1, 1);
        sum1 += __shfl_xor_sync(0xffffffffu, sum1, 2);
        float rv0 = 1.0f / sum0, rv1 = 1.0f / sum1;
        #pragma unroll
        for (int nt = 0; nt < 26; nt++) {
            sc[nt][0] *= rv0; sc[nt][1] *= rv0;
            sc[nt][2] *= rv1; sc[nt][3] *= rv1;
        }

        float oacc[8][4];
        #pragma unroll
        for (int i = 0; i < 8; i++)
            #pragma unroll
            for (int jx = 0; jx < 4; jx++) oacc[i][jx] = 0.f;

        for (int J = 0; J < 13; J++) {
            uint32_t pa_h[4], pa_l[4];
            {
                float p00 = sc[2*J][0],   p01 = sc[2*J][1];
                float p10 = sc[2*J][2],   p11 = sc[2*J][3];
                float p20 = sc[2*J+1][0], p21 = sc[2*J+1][1];
                float p30 = sc[2*J+1][2], p31 = sc[2*J+1][3];
                __nv_bfloat16 hh;
                float l00, l01, l10, l11, l20, l21, l30, l31;
                hh = __float2bfloat16(p00); l00 = p00 - __bfloat162float(hh);
                hh = __float2bfloat16(p01); l01 = p01 - __bfloat162float(hh);
                hh = __float2bfloat16(p10); l10 = p10 - __bfloat162float(hh);
                hh = __float2bfloat16(p11); l11 = p11 - __bfloat162float(hh);
                hh = __float2bfloat16(p20); l20 = p20 - __bfloat162float(hh);
                hh = __float2bfloat16(p21); l21 = p21 - __bfloat162float(hh);
                hh = __float2bfloat16(p30); l30 = p30 - __bfloat162float(hh);
                hh = __float2bfloat16(p31); l31 = p31 - __bfloat162float(hh);
                pa_h[0] = pack_bf16(p00, p01);
                pa_h[1] = pack_bf16(p10, p11);
                pa_h[2] = pack_bf16(p20, p21);
                pa_h[3] = pack_bf16(p30, p31);
                pa_l[0] = pack_bf16(l00, l01);
                pa_l[1] = pack_bf16(l10, l11);
                pa_l[2] = pack_bf16(l20, l21);
                pa_l[3] = pack_bf16(l30, l31);
            }
            uint32_t vb = J * (16 * ALD) + voff;
            #pragma unroll
            for (int np = 0; np < 4; np++) {
                uint32_t bh[4], bl[4];
                ldsm4t(bh, svh + vb + np * 32);
                ldsm4t(bl, svl + vb + np * 32);
                mma_bf16(oacc[2*np],   pa_h, bh[0], bh[1]);
                mma_bf16(oacc[2*np],   pa_h, bl[0], bl[1]);
                mma_bf16(oacc[2*np],   pa_l, bh[0], bh[1]);
                mma_bf16(oacc[2*np+1], pa_h, bh[2], bh[3]);
                mma_bf16(oacc[2*np+1], pa_h, bl[2], bl[3]);
                mma_bf16(oacc[2*np+1], pa_l, bh[2], bh[3]);
            }
        }

        int p0r = m0 + gr, p1r = m0 + gr + 8;
        #pragma unroll
        for (int nt2 = 0; nt2 < 8; nt2++) {
            int n = nt2 * 8 + qc;
            if (p0r < Pp)
                *(float2*)&Ob[(size_t)p0r * Dd + n] = make_float2(oacc[nt2][0], oacc[nt2][1]);
            if (p1r < Pp)
                *(float2*)&Ob[(size_t)p1r * Dd + n] = make_float2(oacc[nt2][2], oacc[nt2][3]);
        }
    }
}

// ---------------- launch ----------------
extern "C" void kernel_launch(void* const* d_in, const int* in_sizes, int n_in,
                              void* d_out, int out_size) {
    const float* x    = (const float*)d_in[0];
    const float* Wq   = (const float*)d_in[1];
    const float* bq   = (const float*)d_in[2];
    const float* Wk   = (const float*)d_in[3];
    const float* bk   = (const float*)d_in[4];
    const float* Wv   = (const float*)d_in[5];
    const float* bv   = (const float*)d_in[6];
    const float* in_a = (const float*)d_in[7];
    const float* in_b = (const float*)d_in[8];
    const float* at_a = (const float*)d_in[9];
    const float* at_b = (const float*)d_in[10];
    const float* ou_a = (const float*)d_in[11];
    const float* ou_b = (const float*)d_in[12];
    const float* Wt   = (const float*)d_in[13];
    const float* bt   = (const float*)d_in[14];
    const float* pos  = (const float*)d_in[15];
    const float* W1   = (const float*)d_in[16];
    const float* b1   = (const float*)d_in[17];
    const float* W2   = (const float*)d_in[18];
    const float* b2   = (const float*)d_in[19];

    float *pav, *pxres, *pbtsum, *pbqkv;
    __nv_bfloat16 *px2h, *px2l, *pyh, *pyl, *phh, *phl, *pwh, *pwl;
    cudaGetSymbolAddress((void**)&pav,  g_av);
    cudaGetSymbolAddress((void**)&pxres,g_xres);
    cudaGetSymbolAddress((void**)&pbtsum, g_btsum);
    cudaGetSymbolAddress((void**)&pbqkv, g_bqkv);
    cudaGetSymbolAddress((void**)&px2h, g_x2h);
    cudaGetSymbolAddress((void**)&px2l, g_x2l);
    cudaGetSymbolAddress((void**)&pyh,  g_yh);
    cudaGetSymbolAddress((void**)&pyl,  g_yl);
    cudaGetSymbolAddress((void**)&phh,  g_hh);
    cudaGetSymbolAddress((void**)&phl,  g_hl);
    cudaGetSymbolAddress((void**)&pwh,  w_hi);
    cudaGetSymbolAddress((void**)&pwl,  w_lo);

    cudaFuncSetAttribute(attn_mma_k, cudaFuncAttributeMaxDynamicSharedMemorySize,
                         ATT_SMEM);
    cudaFuncSetAttribute(gemm_mma_k, cudaFuncAttributeMaxDynamicSharedMemorySize,
                         GM_SMEM);

    // (0) QKV weights+bias convert
    wcvt_qkv_k<<<3072, 256>>>(Wq, Wk, Wv, bq, bk, bv);
    // (1) LN(x) -> x2 hi/lo
    ln_bf_k<<<M1 / 8, 256>>>(x, in_a, in_b, nullptr, px2h, px2l, 1);
    // (2) merged QKV projection (mode 5), N = 1536
    dim3 gq(1536 / 128, (M1 + 127) / 128);
    gemm_mma_k<<<gq, 256, GM_SMEM>>>(px2h, px2l, pwh + OQ, pwl + OQ, pbqkv, nullptr,
                                     nullptr, nullptr, nullptr, M1, 1536, Dd, 5);
    // (3) tensor-core attention -> g_av  (ncu capture slot)
    attn_mma_k<<<Bq * Tt * Tt * Hh, 256, ATT_SMEM>>>();
    // (4) remaining weights convert
    wcvt_rest_k<<<16384, 256>>>(Wt, W1, W2);
    // (5) bt sum
    btsum_k<<<2, 256>>>(bt);
    // (6) LN(av)+pos -> y hi/lo
    ln_bf_k<<<ROWS_AV / 8, 256>>>(pav, at_a, at_b, pos, pyh, pyl, POSMOD);
    // (7) tc contraction (mode 1)
    dim3 gtc(Dd / 128, (M1 + 127) / 128);
    gemm_mma_k<<<gtc, 256, GM_SMEM>>>(pyh, pyl, pwh + OT, pwl + OT, pbtsum, x,
                                      pxres, nullptr, nullptr, M1, Dd, Tt * Dd, 1);
    // (8) LN(xres) -> x2 hi/lo
    ln_bf_k<<<M1 / 8, 256>>>(pxres, ou_a, ou_b, nullptr, px2h, px2l, 1);
    // (9) MLP1 (mode 2)
    dim3 g1(2 * Dd / 128, (M1 + 127) / 128);
    gemm_mma_k<<<g1, 256, GM_SMEM>>>(px2h, px2l, pwh + O1, pwl + O1, b1, nullptr,
                                     nullptr, phh, phl, M1, 2 * Dd, Dd, 2);
    // (10) MLP2 (mode 3) -> d_out
    gemm_mma_k<<<gtc, 256, GM_SMEM>>>(phh, phl, pwh + O2, pwl + O2, b2, pxres,
                                      (float*)d_out, nullptr, nullptr, M1, Dd, 2 * Dd, 3);
}

// round 8
// speedup vs baseline: 4.4790x; 1.0627x over previous
#include <cuda_runtime.h>
#include <cuda_bf16.h>
#include <math.h>
#include <stdint.h>

#define Bq 4
#define Tt 12
#define Pp 196
#define Dd 512
#define Hh 8
#define DHd 64
#define EPSV 1e-6f

#define M1 (Bq*Tt*Pp)            // 9408
#define ROWS_AV (Bq*Tt*Tt*Pp)    // 112896
#define POSMOD (Tt*Tt*Pp)        // 28224

// weight offsets in converted buffer
#define OQ 0
#define OKo 262144
#define OV  524288
#define OT  786432
#define O1  3932160
#define O2  4456448
#define WTOT 4980736

// ---------------- scratch ----------------
__device__ float g_av[(size_t)ROWS_AV*Dd];
__device__ float g_xres[M1*Dd];
__device__ float g_btsum[Dd];
__device__ float g_bqkv[3*Dd];
__device__ __nv_bfloat16 g_x2h[M1*Dd],  g_x2l[M1*Dd];
__device__ __nv_bfloat16 g_qh[M1*Dd], g_ql[M1*Dd];
__device__ __nv_bfloat16 g_kh[M1*Dd], g_kl[M1*Dd];
__device__ __nv_bfloat16 g_vh[M1*Dd], g_vl[M1*Dd];
__device__ __nv_bfloat16 g_yh[(size_t)ROWS_AV*Dd], g_yl[(size_t)ROWS_AV*Dd];
__device__ __nv_bfloat16 g_hh[M1*2*Dd], g_hl[M1*2*Dd];
__device__ __nv_bfloat16 w_hi[WTOT], w_lo[WTOT];

// ---------------- helpers ----------------
__device__ __forceinline__ float gelu_exact(float x) {
    return 0.5f * x * (1.0f + erff(x * 0.70710678118654752f));
}
__device__ __forceinline__ uint32_t smem_u32(const void* p) {
    uint32_t a;
    asm("{ .reg .u64 t; cvta.to.shared.u64 t, %1; cvt.u32.u64 %0, t; }" : "=r"(a) : "l"(p));
    return a;
}
__device__ __forceinline__ void ldsm4(uint32_t* r, uint32_t a) {
    asm volatile("ldmatrix.sync.aligned.m8n8.x4.shared.b16 {%0,%1,%2,%3}, [%4];"
                 : "=r"(r[0]), "=r"(r[1]), "=r"(r[2]), "=r"(r[3]) : "r"(a));
}
__device__ __forceinline__ void ldsm4t(uint32_t* r, uint32_t a) {
    asm volatile("ldmatrix.sync.aligned.m8n8.x4.trans.shared.b16 {%0,%1,%2,%3}, [%4];"
                 : "=r"(r[0]), "=r"(r[1]), "=r"(r[2]), "=r"(r[3]) : "r"(a));
}
__device__ __forceinline__ void mma_bf16(float* c, const uint32_t* a, uint32_t b0, uint32_t b1) {
    asm volatile(
        "mma.sync.aligned.m16n8k16.row.col.f32.bf16.bf16.f32 "
        "{%0,%1,%2,%3}, {%4,%5,%6,%7}, {%8,%9}, {%0,%1,%2,%3};"
        : "+f"(c[0]), "+f"(c[1]), "+f"(c[2]), "+f"(c[3])
        : "r"(a[0]), "r"(a[1]), "r"(a[2]), "r"(a[3]), "r"(b0), "r"(b1));
}
__device__ __forceinline__ void cpa16(uint32_t s, const void* g) {
    asm volatile("cp.async.cg.shared.global [%0], [%1], 16;" :: "r"(s), "l"(g));
}
#define CPA_COMMIT() asm volatile("cp.async.commit_group;" ::: "memory")
#define CPA_WAIT(n)  asm volatile("cp.async.wait_group %0;" :: "n"(n) : "memory")

__device__ __forceinline__ uint32_t pack_bf16(float a, float b) {
    __nv_bfloat162 t = __floats2bfloat162_rn(a, b);
    return *(uint32_t*)&t;
}

// ---------------- bt sum ----------------
__global__ void btsum_k(const float* __restrict__ bt) {
    int e = blockIdx.x * blockDim.x + threadIdx.x;
    if (e < Dd) {
        float s = 0.f;
        #pragma unroll
        for (int u = 0; u < Tt; u++) s += bt[u * Dd + e];
        g_btsum[e] = s;
    }
}

// ---------------- QKV weight + bias convert ----------------
__global__ void wcvt_qkv_k(const float* __restrict__ Wq, const float* __restrict__ Wk,
                           const float* __restrict__ Wv,
                           const float* __restrict__ bq, const float* __restrict__ bk,
                           const float* __restrict__ bv) {
    int i = blockIdx.x * 256 + threadIdx.x;
    if (i < 3 * Dd)
        g_bqkv[i] = (i < Dd) ? bq[i] : (i < 2 * Dd) ? bk[i - Dd] : bv[i - 2 * Dd];
    if (i < 786432) {
        int seg = i >> 18, off = i & 262143;
        float v = (seg == 0) ? Wq[off] : (seg == 1) ? Wk[off] : Wv[off];
        __nv_bfloat16 h = __float2bfloat16(v);
        w_hi[i] = h;
        w_lo[i] = __float2bfloat16(v - __bfloat162float(h));
    }
}

// ---------------- Wt/W1/W2 convert ----------------
__global__ void wcvt_rest_k(const float* __restrict__ Wt, const float* __restrict__ W1,
                            const float* __restrict__ W2) {
    int i = blockIdx.x * 256 + threadIdx.x;  // < 4194304
    float v; int di;
    if (i < 3145728)      { v = Wt[i];            di = OT + i; }
    else if (i < 3670016) { v = W1[i - 3145728];  di = O1 + (i - 3145728); }
    else                  { v = W2[i - 3670016];  di = O2 + (i - 3670016); }
    __nv_bfloat16 h = __float2bfloat16(v);
    w_hi[di] = h;
    w_lo[di] = __float2bfloat16(v - __bfloat162float(h));
}

// ---------------- LayerNorm: warp-per-row -> bf16 hi/lo (+pos) ----------------
__global__ void ln_bf_k(const float* __restrict__ in,
                        const float* __restrict__ al,
                        const float* __restrict__ be,
                        const float* __restrict__ pos,
                        __nv_bfloat16* __restrict__ oh,
                        __nv_bfloat16* __restrict__ ol,
                        int posmod) {
    int w = threadIdx.x >> 5, lane = threadIdx.x & 31;
    int row = blockIdx.x * 8 + w;
    const float* rp = in + (size_t)row * Dd;
    float4 v[4];
    float s = 0.f, sq = 0.f;
    #pragma unroll
    for (int j = 0; j < 4; j++) {
        v[j] = *(const float4*)&rp[lane * 4 + j * 128];
        s  += v[j].x + v[j].y + v[j].z + v[j].w;
        sq += v[j].x*v[j].x + v[j].y*v[j].y + v[j].z*v[j].z + v[j].w*v[j].w;
    }
    #pragma unroll
    for (int o = 16; o; o >>= 1) {
        s  += __shfl_xor_sync(0xffffffffu, s,  o);
        sq += __shfl_xor_sync(0xffffffffu, sq, o);
    }
    float mu  = s * (1.0f / Dd);
    float var = (sq - (float)Dd * mu * mu) * (1.0f / (Dd - 1));
    float inv = 1.0f / (sqrtf(fmaxf(var, 0.f)) + EPSV);
    const float* pp = pos ? (pos + (size_t)(row % posmod) * Dd) : nullptr;

    #pragma unroll
    for (int j = 0; j < 4; j++) {
        int c = lane * 4 + j * 128;
        float4 a = *(const float4*)&al[c];
        float4 b = *(const float4*)&be[c];
        float o0 = a.x * (v[j].x - mu) * inv + b.x;
        float o1 = a.y * (v[j].y - mu) * inv + b.y;
        float o2 = a.z * (v[j].z - mu) * inv + b.z;
        float o3 = a.w * (v[j].w - mu) * inv + b.w;
        if (pp) {
            float4 p = *(const float4*)&pp[c];
            o0 += p.x; o1 += p.y; o2 += p.z; o3 += p.w;
        }
        __nv_bfloat16 h0 = __float2bfloat16(o0);
        __nv_bfloat16 h1 = __float2bfloat16(o1);
        __nv_bfloat16 h2 = __float2bfloat16(o2);
        __nv_bfloat16 h3 = __float2bfloat16(o3);
        uint2 hv, lv;
        __nv_bfloat162 hh01 = __nv_bfloat162(h0, h1);
        __nv_bfloat162 hh23 = __nv_bfloat162(h2, h3);
        hv.x = *(uint32_t*)&hh01;
        hv.y = *(uint32_t*)&hh23;
        __nv_bfloat162 ll01 = __floats2bfloat162_rn(o0 - __bfloat162float(h0),
                                                    o1 - __bfloat162float(h1));
        __nv_bfloat162 ll23 = __floats2bfloat162_rn(o2 - __bfloat162float(h2),
                                                    o3 - __bfloat162float(h3));
        lv.x = *(uint32_t*)&ll01;
        lv.y = *(uint32_t*)&ll23;
        *(uint2*)&oh[(size_t)row * Dd + c] = hv;
        *(uint2*)&ol[(size_t)row * Dd + c] = lv;
    }
}

// ================= mma.sync bf16x3 GEMM ======================
// modes: 0: Cf = acc + bias
//        1 (tc): Cf = res + gelu(acc/12 + bias); A is [b,t,u,p,d], B per-u
//        2: Chi/Clo = split(gelu(acc + bias))
//        3: Cf = res + gelu(acc + bias)
//        5 (qkv): split(acc + bias) routed to g_q/g_k/g_v hi/lo by n>>9
#define LDSE 72
#define TILE_B (128*LDSE*2)
#define STAGE_B (4*TILE_B)
#define GM_SMEM (2*STAGE_B)

__global__ void __launch_bounds__(256, 1) gemm_mma_k(
    const __nv_bfloat16* __restrict__ Ahi, const __nv_bfloat16* __restrict__ Alo,
    const __nv_bfloat16* __restrict__ Bhi, const __nv_bfloat16* __restrict__ Blo,
    const float* __restrict__ bias, const float* __restrict__ res,
    float* __restrict__ Cf, __nv_bfloat16* __restrict__ Chi, __nv_bfloat16* __restrict__ Clo,
    int M, int N, int K, int mode)
{
    extern __shared__ char smc[];
    int tid = threadIdx.x;
    int wid = tid >> 5, lane = tid & 31;
    int bm = blockIdx.y * 128, bn = blockIdx.x * 128;
    int wm = (wid >> 2) * 64;
    int wn = (wid & 3) * 32;

    int lrow = tid >> 1;
    int lhalf = tid & 1;
    int am = min(bm + lrow, M - 1);
    size_t abase;
    if (mode == 1) {
        int b_ = am / (Tt * Pp), r_ = am % (Tt * Pp);
        int t_ = r_ / Pp, p_ = r_ % Pp;
        abase = ((size_t)(b_ * (Tt * Tt) + t_ * Tt) * Pp + p_) * Dd;
    } else {
        abase = (size_t)am * K;
    }
    int brow = bn + lrow;
    uint32_t smrow = lrow * (LDSE * 2);

    int NC = K / 64;

    auto load_stage = [&](int buf, int c) {
        size_t aoff, boff;
        if (mode == 1) {
            int u = c >> 3, d0 = (c & 7) * 64;
            aoff = abase + (size_t)u * (Pp * Dd) + d0;
            boff = (size_t)u * (Dd * Dd) + (size_t)brow * Dd + d0;
        } else {
            aoff = abase + c * 64;
            boff = (size_t)brow * K + c * 64;
        }
        uint32_t sb = smem_u32(smc) + buf * STAGE_B + smrow;
        #pragma unroll
        for (int i = 0; i < 4; i++) {
            int colk = lhalf * 32 + i * 8;
            uint32_t so = sb + colk * 2;
            cpa16(so,              Ahi + aoff + colk);
            cpa16(so + TILE_B,     Alo + aoff + colk);
            cpa16(so + 2*TILE_B,   Bhi + boff + colk);
            cpa16(so + 3*TILE_B,   Blo + boff + colk);
        }
    };

    int sel = lane >> 3, lr = lane & 7;
    int a_m = wm + (sel & 1) * 8 + lr;
    int a_k = (sel >> 1) * 8;
    int b_n = wn + (sel >> 1) * 8 + lr;
    int b_k = (sel & 1) * 8;
    uint32_t smb = smem_u32(smc);
    uint32_t aoffB = (a_m * LDSE + a_k) * 2;
    uint32_t boffB = (b_n * LDSE + b_k) * 2;

    float acc[4][4][4] = {};

    load_stage(0, 0);
    CPA_COMMIT();

    for (int c = 0; c < NC; c++) {
        int buf = c & 1;
        if (c + 1 < NC) {
            load_stage(buf ^ 1, c + 1);
            CPA_COMMIT();
            CPA_WAIT(1);
        } else {
            CPA_WAIT(0);
        }
        __syncthreads();

        uint32_t base = smb + buf * STAGE_B;
        uint32_t aHb = base + aoffB;
        uint32_t aLb = aHb + TILE_B;
        uint32_t bHb = base + 2*TILE_B + boffB;
        uint32_t bLb = bHb + TILE_B;

        #pragma unroll
        for (int kk = 0; kk < 4; kk++) {
            uint32_t ko = kk * 32;
            uint32_t aH[4][4], aL[4][4], bH[2][4], bL[2][4];
            #pragma unroll
            for (int mt = 0; mt < 4; mt++) {
                ldsm4(aH[mt], aHb + mt * (16 * LDSE * 2) + ko);
                ldsm4(aL[mt], aLb + mt * (16 * LDSE * 2) + ko);
            }
            #pragma unroll
            for (int nt2 = 0; nt2 < 2; nt2++) {
                ldsm4(bH[nt2], bHb + nt2 * (16 * LDSE * 2) + ko);
                ldsm4(bL[nt2], bLb + nt2 * (16 * LDSE * 2) + ko);
            }
            // term-major issue: same-accumulator RAW distance = 16
            #pragma unroll
            for (int mt = 0; mt < 4; mt++)
                #pragma unroll
                for (int nt = 0; nt < 4; nt++) {
                    int s2 = nt >> 1, pp = (nt & 1) * 2;
                    mma_bf16(acc[mt][nt], aH[mt], bH[s2][pp], bH[s2][pp+1]);
                }
            #pragma unroll
            for (int mt = 0; mt < 4; mt++)
                #pragma unroll
                for (int nt = 0; nt < 4; nt++) {
                    int s2 = nt >> 1, pp = (nt & 1) * 2;
                    mma_bf16(acc[mt][nt], aH[mt], bL[s2][pp], bL[s2][pp+1]);
                }
            #pragma unroll
            for (int mt = 0; mt < 4; mt++)
                #pragma unroll
                for (int nt = 0; nt < 4; nt++) {
                    int s2 = nt >> 1, pp = (nt & 1) * 2;
                    mma_bf16(acc[mt][nt], aL[mt], bH[s2][pp], bH[s2][pp+1]);
                }
        }
        __syncthreads();
    }

    int qrow = lane >> 2;
    int qcol = (lane & 3) * 2;
    #pragma unroll
    for (int mt = 0; mt < 4; mt++) {
        #pragma unroll
        for (int nt = 0; nt < 4; nt++) {
            float* cc = acc[mt][nt];
            int n0 = bn + wn + nt * 8 + qcol;
            float b0 = bias[n0], b1 = bias[n0 + 1];
            #pragma unroll
            for (int hrow = 0; hrow < 2; hrow++) {
                int m = bm + wm + mt * 16 + qrow + hrow * 8;
                if (m >= M) continue;
                float a0 = cc[hrow * 2 + 0];
                float a1 = cc[hrow * 2 + 1];
                float v0, v1;
                if (mode == 0) {
                    size_t off = (size_t)m * N + n0;
                    v0 = a0 + b0; v1 = a1 + b1;
                    *(float2*)&Cf[off] = make_float2(v0, v1);
                } else if (mode == 1) {
                    size_t off = (size_t)m * N + n0;
                    float2 r = *(const float2*)&res[off];
                    v0 = r.x + gelu_exact(a0 * (1.0f / Tt) + b0);
                    v1 = r.y + gelu_exact(a1 * (1.0f / Tt) + b1);
                    *(float2*)&Cf[off] = make_float2(v0, v1);
                } else if (mode == 3) {
                    size_t off = (size_t)m * N + n0;
                    float2 r = *(const float2*)&res[off];
                    v0 = r.x + gelu_exact(a0 + b0);
                    v1 = r.y + gelu_exact(a1 + b1);
                    *(float2*)&Cf[off] = make_float2(v0, v1);
                } else if (mode == 5) {
                    int seg = n0 >> 9, nn = n0 & 511;
                    __nv_bfloat16* dh = (seg == 0) ? g_qh : (seg == 1) ? g_kh : g_vh;
                    __nv_bfloat16* dl = (seg == 0) ? g_ql : (seg == 1) ? g_kl : g_vl;
                    float g0 = a0 + b0, g1 = a1 + b1;
                    __nv_bfloat16 h0 = __float2bfloat16(g0);
                    __nv_bfloat16 h1 = __float2bfloat16(g1);
                    __nv_bfloat162 hh = __nv_bfloat162(h0, h1);
                    __nv_bfloat162 ll = __floats2bfloat162_rn(g0 - __bfloat162float(h0),
                                                              g1 - __bfloat162float(h1));
                    size_t off = (size_t)m * Dd + nn;
                    *(__nv_bfloat162*)(dh + off) = hh;
                    *(__nv_bfloat162*)(dl + off) = ll;
                } else { // mode 2
                    size_t off = (size_t)m * N + n0;
                    float g0 = gelu_exact(a0 + b0);
                    float g1 = gelu_exact(a1 + b1);
                    __nv_bfloat16 h0 = __float2bfloat16(g0);
                    __nv_bfloat16 h1 = __float2bfloat16(g1);
                    __nv_bfloat162 hh = __nv_bfloat162(h0, h1);
                    __nv_bfloat162 ll = __floats2bfloat162_rn(g0 - __bfloat162float(h0),
                                                              g1 - __bfloat162float(h1));
                    *(__nv_bfloat162*)(Chi + off) = hh;
                    *(__nv_bfloat162*)(Clo + off) = ll;
                }
            }
        }
    }
}

// ================= tensor-core attention (bf16x3) ======================
// one block per (b, t-group-of-4, u, h); 8 warps; 52 q-tiles of 16.
// K and V row-major [208][72] bf16 hi/lo in smem (144B rows), loaded once.
#define AKR 208
#define ALD 144
#define ASM_ONE (AKR*ALD)
#define ATT_SMEM (4*ASM_ONE)
#define TG 4

__global__ void __launch_bounds__(256, 1) attn_mma_k() {
    int bid = blockIdx.x;
    int h = bid & 7;
    int u = (bid >> 3) % Tt;
    int tg = (bid / (8 * Tt)) % (Tt / TG);
    int b = bid / (8 * Tt * (Tt / TG));

    extern __shared__ char smb_[];
    uint32_t skh = smem_u32(smb_);
    uint32_t skl = skh + ASM_ONE;
    uint32_t svh = skh + 2 * ASM_ONE;
    uint32_t svl = skh + 3 * ASM_ONE;

    int tid = threadIdx.x;
    int w = tid >> 5, lane = tid & 31;

    size_t kvbase = ((size_t)(b * Tt + u) * Pp) * Dd + h * DHd;

    for (int idx = tid; idx < AKR * 8; idx += 256) {
        int row = idx >> 3, seg = idx & 7;
        uint4 kh4 = make_uint4(0,0,0,0), kl4 = kh4, vh4 = kh4, vl4 = kh4;
        if (row < Pp) {
            size_t g = kvbase + (size_t)row * Dd + seg * 8;
            kh4 = *(const uint4*)&g_kh[g];
            kl4 = *(const uint4*)&g_kl[g];
            vh4 = *(const uint4*)&g_vh[g];
            vl4 = *(const uint4*)&g_vl[g];
        }
        uint32_t so = row * ALD + seg * 16;
        *(uint4*)(smb_ + so) = kh4;
        *(uint4*)(smb_ + ASM_ONE + so) = kl4;
        *(uint4*)(smb_ + 2*ASM_ONE + so) = vh4;
        *(uint4*)(smb_ + 3*ASM_ONE + so) = vl4;
    }
    __syncthreads();

    int gr = lane >> 2, qc = (lane & 3) * 2;
    int sel = lane >> 3, lr = lane & 7;
    uint32_t koff = ((sel >> 1) * 8 + lr) * ALD + (sel & 1) * 16;
    uint32_t voff = ((sel & 1) * 8 + lr) * ALD + (sel >> 1) * 16;

    for (int tau = w; tau < 13 * TG; tau += 8) {
        int tl = tau / 13, mt = tau % 13;
        int t = tg * TG + tl;
        size_t qbase = ((size_t)(b * Tt + t) * Pp) * Dd + h * DHd;
        float* Ob = g_av + ((size_t)((b * Tt + t) * Tt + u) * Pp) * Dd + h * DHd;

        int m0 = mt * 16;
        int r0 = min(m0 + gr, Pp - 1);
        int r1 = min(m0 + gr + 8, Pp - 1);

        uint32_t qa_h[4][4], qa_l[4][4];
        #pragma unroll
        for (int J = 0; J < 4; J++) {
            int c0 = J * 16 + qc;
            qa_h[J][0] = *(const uint32_t*)&g_qh[qbase + (size_t)r0 * Dd + c0];
            qa_h[J][1] = *(const uint32_t*)&g_qh[qbase + (size_t)r1 * Dd + c0];
            qa_h[J][2] = *(const uint32_t*)&g_qh[qbase + (size_t)r0 * Dd + c0 + 8];
            qa_h[J][3] = *(const uint32_t*)&g_qh[qbase + (size_t)r1 * Dd + c0 + 8];
            qa_l[J][0] = *(const uint32_t*)&g_ql[qbase + (size_t)r0 * Dd + c0];
            qa_l[J][1] = *(const uint32_t*)&g_ql[qbase + (size_t)r1 * Dd + c0];
            qa_l[J][2] = *(const uint32_t*)&g_ql[qbase + (size_t)r0 * Dd + c0 + 8];
            qa_l[J][3] = *(const uint32_t*)&g_ql[qbase + (size_t)r1 * Dd + c0 + 8];
        }

        float sc[26][4];
        #pragma unroll
        for (int nt = 0; nt < 26; nt++)
            #pragma unroll
            for (int i = 0; i < 4; i++) sc[nt][i] = 0.f;

        // QK^T: ntp pairs, term-major (same-acc RAW distance 4)
        #pragma unroll
        for (int J = 0; J < 4; J++) {
            for (int ntp = 0; ntp < 12; ntp += 2) {
                uint32_t kb0 = ntp * (16 * ALD) + koff + J * 32;
                uint32_t kb1 = kb0 + 16 * ALD;
                uint32_t bh0[4], bl0[4], bh1[4], bl1[4];
                ldsm4(bh0, skh + kb0);
                ldsm4(bl0, skl + kb0);
                ldsm4(bh1, skh + kb1);
                ldsm4(bl1, skl + kb1);
                mma_bf16(sc[2*ntp],   qa_h[J], bh0[0], bh0[1]);
                mma_bf16(sc[2*ntp+1], qa_h[J], bh0[2], bh0[3]);
                mma_bf16(sc[2*ntp+2], qa_h[J], bh1[0], bh1[1]);
                mma_bf16(sc[2*ntp+3], qa_h[J], bh1[2], bh1[3]);
                mma_bf16(sc[2*ntp],   qa_h[J], bl0[0], bl0[1]);
                mma_bf16(sc[2*ntp+1], qa_h[J], bl0[2], bl0[3]);
                mma_bf16(sc[2*ntp+2], qa_h[J], bl1[0], bl1[1]);
                mma_bf16(sc[2*ntp+3], qa_h[J], bl1[2], bl1[3]);
                mma_bf16(sc[2*ntp],   qa_l[J], bh0[0], bh0[1]);
                mma_bf16(sc[2*ntp+1], qa_l[J], bh0[2], bh0[3]);
                mma_bf16(sc[2*ntp+2], qa_l[J], bh1[0], bh1[1]);
                mma_bf16(sc[2*ntp+3], qa_l[J], bh1[2], bh1[3]);
            }
            { // tail ntp = 12
                uint32_t kb = 12 * (16 * ALD) + koff + J * 32;
                uint32_t bh[4], bl[4];
                ldsm4(bh, skh + kb);
                ldsm4(bl, skl + kb);
                mma_bf16(sc[24], qa_h[J], bh[0], bh[1]);
                mma_bf16(sc[25], qa_h[J], bh[2], bh[3]);
                mma_bf16(sc[24], qa_h[J], bl[0], bl[1]);
                mma_bf16(sc[25], qa_h[J], bl[2], bl[3]);
                mma_bf16(sc[24], qa_l[J], bh[0], bh[1]);
                mma_bf16(sc[25], qa_l[J], bh[2], bh[3]);
            }
        }

        float mx0 = -1e30f, mx1 = -1e30f;
        #pragma unroll
        for (int nt = 0; nt < 26; nt++) {
            int n0 = nt * 8 + qc;
            if (n0 >= Pp) {
                sc[nt][0] = sc[nt][1] = sc[nt][2] = sc[nt][3] = -1e30f;
            } else {
                sc[nt][0] *= 0.125f; sc[nt][1] *= 0.125f;
                sc[nt][2] *= 0.125f; sc[nt][3] *= 0.125f;
            }
            mx0 = fmaxf(mx0, fmaxf(sc[nt][0], sc[nt][1]));
            mx1 = fmaxf(mx1, fmaxf(sc[nt][2], sc[nt][3]));
        }
        mx0 = fmaxf(mx0, __shfl_xor_sync(0xffffffffu, mx0, 1));
        mx0 = fmaxf(mx0, __shfl_xor_sync(0xffffffffu, mx0, 2));
        mx1 = fmaxf(mx1, __shfl_xor_sync(0xffffffffu, mx1, 1));
        mx1 = fmaxf(mx1, __shfl_xor_sync(0xffffffffu, mx1, 2));
        float sum0 = 0.f, sum1 = 0.f;
        #pragma unroll
        for (int nt = 0; nt < 26; nt++) {
            sc[nt][0] = __expf(sc[nt][0] - mx0);
            sc[nt][1] = __expf(sc[nt][1] - mx0);
            sc[nt][2] = __expf(sc[nt][2] - mx1);
            sc[nt][3] = __expf(sc[nt][3] - mx1);
            sum0 += sc[nt][0] + sc[nt][1];
            sum1 += sc[nt][2] + sc[nt][3];
        }
        sum0 += __shfl_xor_sync(0xffffffffu, sum0, 1);
        sum0 += __shfl_xor_sync(0xffffffffu, sum0, 2);
        sum1 += __shfl_xor_sync(0xffffffffu, sum1, 1);
        sum1 += __shfl_xor_sync(0xffffffffu, sum1, 2);
        float rv0 = 1.0f / sum0, rv1 = 1.0f / sum1;
        #pragma unroll
        for (int nt = 0; nt < 26; nt++) {
            sc[nt][0] *= rv0; sc[nt][1] *= rv0;
            sc[nt][2] *= rv1; sc[nt][3] *= rv1;
        }

        float oacc[8][4];
        #pragma unroll
        for (int i = 0; i < 8; i++)
            #pragma unroll
            for (int jx = 0; jx < 4; jx++) oacc[i][jx] = 0.f;

        for (int J = 0; J < 13; J++) {
            uint32_t pa_h[4], pa_l[4];
            {
                float p00 = sc[2*J][0],   p01 = sc[2*J][1];
                float p10 = sc[2*J][2],   p11 = sc[2*J][3];
                float p20 = sc[2*J+1][0], p21 = sc[2*J+1][1];
                float p30 = sc[2*J+1][2], p31 = sc[2*J+1][3];
                __nv_bfloat16 hh;
                float l00, l01, l10, l11, l20, l21, l30, l31;
                hh = __float2bfloat16(p00); l00 = p00 - __bfloat162float(hh);
                hh = __float2bfloat16(p01); l01 = p01 - __bfloat162float(hh);
                hh = __float2bfloat16(p10); l10 = p10 - __bfloat162float(hh);
                hh = __float2bfloat16(p11); l11 = p11 - __bfloat162float(hh);
                hh = __float2bfloat16(p20); l20 = p20 - __bfloat162float(hh);
                hh = __float2bfloat16(p21); l21 = p21 - __bfloat162float(hh);
                hh = __float2bfloat16(p30); l30 = p30 - __bfloat162float(hh);
                hh = __float2bfloat16(p31); l31 = p31 - __bfloat162float(hh);
                pa_h[0] = pack_bf16(p00, p01);
                pa_h[1] = pack_bf16(p10, p11);
                pa_h[2] = pack_bf16(p20, p21);
                pa_h[3] = pack_bf16(p30, p31);
                pa_l[0] = pack_bf16(l00, l01);
                pa_l[1] = pack_bf16(l10, l11);
                pa_l[2] = pack_bf16(l20, l21);
                pa_l[3] = pack_bf16(l30, l31);
            }
            uint32_t vb = J * (16 * ALD) + voff;
            uint32_t bh[4][4], bl[4][4];
            #pragma unroll
            for (int np = 0; np < 4; np++) {
                ldsm4t(bh[np], svh + vb + np * 32);
                ldsm4t(bl[np], svl + vb + np * 32);
            }
            // term-major: same-acc RAW distance 8
            #pragma unroll
            for (int np = 0; np < 4; np++) {
                mma_bf16(oacc[2*np],   pa_h, bh[np][0], bh[np][1]);
                mma_bf16(oacc[2*np+1], pa_h, bh[np][2], bh[np][3]);
            }
            #pragma unroll
            for (int np = 0; np < 4; np++) {
                mma_bf16(oacc[2*np],   pa_h, bl[np][0], bl[np][1]);
                mma_bf16(oacc[2*np+1], pa_h, bl[np][2], bl[np][3]);
            }
            #pragma unroll
            for (int np = 0; np < 4; np++) {
                mma_bf16(oacc[2*np],   pa_l, bh[np][0], bh[np][1]);
                mma_bf16(oacc[2*np+1], pa_l, bh[np][2], bh[np][3]);
            }
        }

        int p0r = m0 + gr, p1r = m0 + gr + 8;
        #pragma unroll
        for (int nt2 = 0; nt2 < 8; nt2++) {
            int n = nt2 * 8 + qc;
            if (p0r < Pp)
                *(float2*)&Ob[(size_t)p0r * Dd + n] = make_float2(oacc[nt2][0], oacc[nt2][1]);
            if (p1r < Pp)
                *(float2*)&Ob[(size_t)p1r * Dd + n] = make_float2(oacc[nt2][2], oacc[nt2][3]);
        }
    }
}

// ---------------- launch ----------------
extern "C" void kernel_launch(void* const* d_in, const int* in_sizes, int n_in,
                              void* d_out, int out_size) {
    const float* x    = (const float*)d_in[0];
    const float* Wq   = (const float*)d_in[1];
    const float* bq   = (const float*)d_in[2];
    const float* Wk   = (const float*)d_in[3];
    const float* bk   = (const float*)d_in[4];
    const float* Wv   = (const float*)d_in[5];
    const float* bv   = (const float*)d_in[6];
    const float* in_a = (const float*)d_in[7];
    const float* in_b = (const float*)d_in[8];
    const float* at_a = (const float*)d_in[9];
    const float* at_b = (const float*)d_in[10];
    const float* ou_a = (const float*)d_in[11];
    const float* ou_b = (const float*)d_in[12];
    const float* Wt   = (const float*)d_in[13];
    const float* bt   = (const float*)d_in[14];
    const float* pos  = (const float*)d_in[15];
    const float* W1   = (const float*)d_in[16];
    const float* b1   = (const float*)d_in[17];
    const float* W2   = (const float*)d_in[18];
    const float* b2   = (const float*)d_in[19];

    float *pav, *pxres, *pbtsum, *pbqkv;
    __nv_bfloat16 *px2h, *px2l, *pyh, *pyl, *phh, *phl, *pwh, *pwl;
    cudaGetSymbolAddress((void**)&pav,  g_av);
    cudaGetSymbolAddress((void**)&pxres,g_xres);
    cudaGetSymbolAddress((void**)&pbtsum, g_btsum);
    cudaGetSymbolAddress((void**)&pbqkv, g_bqkv);
    cudaGetSymbolAddress((void**)&px2h, g_x2h);
    cudaGetSymbolAddress((void**)&px2l, g_x2l);
    cudaGetSymbolAddress((void**)&pyh,  g_yh);
    cudaGetSymbolAddress((void**)&pyl,  g_yl);
    cudaGetSymbolAddress((void**)&phh,  g_hh);
    cudaGetSymbolAddress((void**)&phl,  g_hl);
    cudaGetSymbolAddress((void**)&pwh,  w_hi);
    cudaGetSymbolAddress((void**)&pwl,  w_lo);

    cudaFuncSetAttribute(attn_mma_k, cudaFuncAttributeMaxDynamicSharedMemorySize,
                         ATT_SMEM);
    cudaFuncSetAttribute(gemm_mma_k, cudaFuncAttributeMaxDynamicSharedMemorySize,
                         GM_SMEM);

    // (0) QKV weights+bias convert
    wcvt_qkv_k<<<3072, 256>>>(Wq, Wk, Wv, bq, bk, bv);
    // (1) LN(x) -> x2 hi/lo
    ln_bf_k<<<M1 / 8, 256>>>(x, in_a, in_b, nullptr, px2h, px2l, 1);
    // (2) merged QKV projection (mode 5), N = 1536
    dim3 gq(1536 / 128, (M1 + 127) / 128);
    gemm_mma_k<<<gq, 256, GM_SMEM>>>(px2h, px2l, pwh + OQ, pwl + OQ, pbqkv, nullptr,
                                     nullptr, nullptr, nullptr, M1, 1536, Dd, 5);
    // (3) tensor-core attention -> g_av  (ncu capture slot)
    attn_mma_k<<<Bq * (Tt / TG) * Tt * Hh, 256, ATT_SMEM>>>();
    // (4) remaining weights convert
    wcvt_rest_k<<<16384, 256>>>(Wt, W1, W2);
    // (5) bt sum
    btsum_k<<<2, 256>>>(bt);
    // (6) LN(av)+pos -> y hi/lo
    ln_bf_k<<<ROWS_AV / 8, 256>>>(pav, at_a, at_b, pos, pyh, pyl, POSMOD);
    // (7) tc contraction (mode 1)
    dim3 gtc(Dd / 128, (M1 + 127) / 128);
    gemm_mma_k<<<gtc, 256, GM_SMEM>>>(pyh, pyl, pwh + OT, pwl + OT, pbtsum, x,
                                      pxres, nullptr, nullptr, M1, Dd, Tt * Dd, 1);
    // (8) LN(xres) -> x2 hi/lo
    ln_bf_k<<<M1 / 8, 256>>>(pxres, ou_a, ou_b, nullptr, px2h, px2l, 1);
    // (9) MLP1 (mode 2)
    dim3 g1(2 * Dd / 128, (M1 + 127) / 128);
    gemm_mma_k<<<g1, 256, GM_SMEM>>>(px2h, px2l, pwh + O1, pwl + O1, b1, nullptr,
                                     nullptr, phh, phl, M1, 2 * Dd, Dd, 2);
    // (10) MLP2 (mode 3) -> d_out
    gemm_mma_k<<<gtc, 256, GM_SMEM>>>(phh, phl, pwh + O2, pwl + O2, b2, pxres,
                                      (float*)d_out, nullptr, nullptr, M1, Dd, 2 * Dd, 3);
}